// round 7
// baseline (speedup 1.0000x reference)
#include <cuda_runtime.h>
#include <math.h>
#include <stdint.h>

#define Nn 20000
#define Ff 32
#define Tt 12
#define Hh 64
#define Ee 320000
#define OUTD 12
#define TN (Tt * Nn)

// ---------------- scratch ----------------
static __device__ float g_xt[(size_t)TN * Ff];
static __device__ float g_deg[Nn];
static __device__ float g_dinv[Nn];
static __device__ float g_norm[Ee];
static __device__ int   g_cnt[Nn];
static __device__ int   g_cur[Nn];
static __device__ int   g_rowptr[Nn + 1];
static __device__ int   g_csrsrc[Ee];
static __device__ float g_csrnorm[Ee];
static __device__ float g_xw0all[(size_t)TN * Hh];
static __device__ float g_g0all[(size_t)TN * Hh];
static __device__ float g_p0all[(size_t)TN * 192];
static __device__ float g_xw[(size_t)Nn * Hh];
static __device__ float g_h0[(size_t)Nn * Hh];
static __device__ float g_h1[(size_t)Nn * Hh];
static __device__ float g_hseq[(size_t)TN * Hh];
static __device__ float g_qkv[(size_t)TN * 192];
static __device__ float g_ipwT[Hh * 192];
static __device__ float g_opwT[Hh * Hh];

// pre-packed tf32 b-fragments
static __device__ unsigned g_pk_Wg0[1 * 2048];
static __device__ unsigned g_pk_pre0[9 * 2048];
static __device__ unsigned g_pk_urc0[6 * 2048];
static __device__ unsigned g_pk_Wg1[2 * 2048];
static __device__ unsigned g_pk_urc1[18 * 2048];
static __device__ unsigned g_pk_qkv[6 * 2048];

__device__ __forceinline__ float sigmoidf_(float x) { return 1.0f / (1.0f + __expf(-x)); }

__device__ __forceinline__ unsigned f2tf32(float f) {
    unsigned r;
    asm("cvt.rna.tf32.f32 %0, %1;" : "=r"(r) : "f"(f));
    return r;
}

__device__ __forceinline__ void mma_tf32(float c[4], const unsigned a[4], unsigned b0, unsigned b1) {
    asm volatile(
        "mma.sync.aligned.m16n8k8.row.col.f32.tf32.tf32.f32 "
        "{%0,%1,%2,%3}, {%4,%5,%6,%7}, {%8,%9}, {%0,%1,%2,%3};"
        : "+f"(c[0]), "+f"(c[1]), "+f"(c[2]), "+f"(c[3])
        : "r"(a[0]), "r"(a[1]), "r"(a[2]), "r"(a[3]), "r"(b0), "r"(b1));
}

__device__ __forceinline__ void load_A_chunk(unsigned a[4][4], const float* __restrict__ A,
                                             int lda, int r0, int r1, bool v0, bool v1,
                                             int k0, int qc) {
#pragma unroll
    for (int s = 0; s < 4; s++) {
        int k = k0 + 8 * s + qc;
        float x0 = v0 ? A[(size_t)r0 * lda + k] : 0.f;
        float x1 = v1 ? A[(size_t)r1 * lda + k] : 0.f;
        float x2 = v0 ? A[(size_t)r0 * lda + k + 4] : 0.f;
        float x3 = v1 ? A[(size_t)r1 * lda + k + 4] : 0.f;
        a[s][0] = f2tf32(x0); a[s][1] = f2tf32(x1);
        a[s][2] = f2tf32(x2); a[s][3] = f2tf32(x3);
    }
}

// A chunk from smem float buffer G[row][68]
__device__ __forceinline__ void load_A_smemF(unsigned a[4][4], const float* G,
                                             int rl0, int k0, int qc) {
#pragma unroll
    for (int s = 0; s < 4; s++) {
        int k = k0 + 8 * s + qc;
        a[s][0] = f2tf32(G[rl0 * 68 + k]);
        a[s][1] = f2tf32(G[(rl0 + 8) * 68 + k]);
        a[s][2] = f2tf32(G[rl0 * 68 + k + 4]);
        a[s][3] = f2tf32(G[(rl0 + 8) * 68 + k + 4]);
    }
}

// A chunk from smem tf32 buffer U[k][136]
__device__ __forceinline__ void load_A_smemU(unsigned a[4][4], const unsigned* U,
                                             int rl0, int k0, int qc) {
#pragma unroll
    for (int s = 0; s < 4; s++) {
        int k = k0 + 8 * s + qc;
        a[s][0] = U[k * 136 + rl0];
        a[s][1] = U[k * 136 + rl0 + 8];
        a[s][2] = U[(k + 4) * 136 + rl0];
        a[s][3] = U[(k + 4) * 136 + rl0 + 8];
    }
}

__device__ __forceinline__ void mma_gate(float C[8][4], const unsigned a[4][4],
                                         const unsigned* __restrict__ Bpk, int lane) {
    const uint4* B4 = (const uint4*)Bpk;
#pragma unroll
    for (int s = 0; s < 4; s++)
#pragma unroll
        for (int f2 = 0; f2 < 4; f2++) {
            uint4 b = B4[(s * 4 + f2) * 32 + lane];
            mma_tf32(C[2 * f2], a[s], b.x, b.y);
            mma_tf32(C[2 * f2 + 1], a[s], b.z, b.w);
        }
}

// ---------------- weight pack ----------------
__global__ void k_pack(const float* __restrict__ W, int ldw, int nch,
                       unsigned* __restrict__ dst) {
    int tid = blockIdx.x * blockDim.x + threadIdx.x;
    if (tid >= nch * 512) return;
    int c = tid >> 9, r = tid & 511;
    int s = r >> 7, f2 = (r >> 5) & 3, lane = r & 31;
    int qr = lane >> 2, qc = lane & 3;
    int k1 = c * 32 + 8 * s + qc, k2 = k1 + 4;
    int n1 = 16 * f2 + qr, n2 = n1 + 8;
    uint4 o;
    o.x = f2tf32(W[(size_t)k1 * ldw + n1]);
    o.y = f2tf32(W[(size_t)k2 * ldw + n1]);
    o.z = f2tf32(W[(size_t)k1 * ldw + n2]);
    o.w = f2tf32(W[(size_t)k2 * ldw + n2]);
    ((uint4*)dst)[tid] = o;
}

// ---------------- preprocessing ----------------
__global__ void k_transpose(const float* __restrict__ x) {
    int idx = blockIdx.x * blockDim.x + threadIdx.x;
    if (idx >= Nn * Ff * Tt) return;
    int f = idx & (Ff - 1);
    int t = (idx / Ff) % Tt;
    int n = idx / (Ff * Tt);
    g_xt[(size_t)t * Nn * Ff + (size_t)n * Ff + f] = x[(size_t)n * Ff * Tt + (size_t)f * Tt + t];
}

__global__ void k_trW(const float* __restrict__ ipw, const float* __restrict__ opw) {
    int i = blockIdx.x * blockDim.x + threadIdx.x;
    if (i < 192 * Hh) { int r = i / Hh, c = i % Hh; g_ipwT[c * 192 + r] = ipw[i]; }
    if (i < Hh * Hh)  { int r = i / Hh, c = i % Hh; g_opwT[c * Hh + r] = opw[i]; }
}

__global__ void k_deg_hist(const int* __restrict__ ei, const float* __restrict__ ea) {
    int e = blockIdx.x * blockDim.x + threadIdx.x;
    if (e >= Ee) return;
    int d = ei[Ee + e];
    atomicAdd(&g_deg[d], ea[2 * e + 1]);
    atomicAdd(&g_cnt[d], 1);
}

__global__ void k_dinv() {
    int n = blockIdx.x * blockDim.x + threadIdx.x;
    if (n < Nn) g_dinv[n] = rsqrtf(g_deg[n] + 1.0f);
}

__global__ void k_norm(const int* __restrict__ ei, const float* __restrict__ ea) {
    int e = blockIdx.x * blockDim.x + threadIdx.x;
    if (e >= Ee) return;
    g_norm[e] = g_dinv[ei[e]] * ea[2 * e + 1] * g_dinv[ei[Ee + e]];
}

__global__ void k_scan() {
    __shared__ int sbuf[1024];
    __shared__ int s_carry;
    int tid = threadIdx.x;
    if (tid == 0) { s_carry = 0; g_rowptr[0] = 0; }
    __syncthreads();
    for (int base = 0; base < Nn; base += 1024) {
        int v = (base + tid < Nn) ? g_cnt[base + tid] : 0;
        sbuf[tid] = v;
        __syncthreads();
        for (int off = 1; off < 1024; off <<= 1) {
            int t2 = (tid >= off) ? sbuf[tid - off] : 0;
            __syncthreads();
            sbuf[tid] += t2;
            __syncthreads();
        }
        int incl = sbuf[tid] + s_carry;
        if (base + tid < Nn) g_rowptr[base + tid + 1] = incl;
        int total = sbuf[1023];
        __syncthreads();
        if (tid == 0) s_carry += total;
        __syncthreads();
    }
}

__global__ void k_fill(const int* __restrict__ ei) {
    int e = blockIdx.x * blockDim.x + threadIdx.x;
    if (e >= Ee) return;
    int d = ei[Ee + e];
    int pos = g_rowptr[d] + atomicAdd(&g_cur[d], 1);
    g_csrsrc[pos] = ei[e];
    g_csrnorm[pos] = g_norm[e];
}

// ---------------- generic MMA GEMM (128-row blocks) -------------------------
__global__ __launch_bounds__(256) void k_mma_g(const float* __restrict__ A, int lda,
                                               int nch, int M,
                                               const unsigned* __restrict__ Bpk,
                                               float* __restrict__ out) {
    int tid = threadIdx.x, lane = tid & 31, w = tid >> 5;
    int qr = lane >> 2, qc = lane & 3;
    int r0 = blockIdx.x * 128 + w * 16 + qr, r1 = r0 + 8;
    bool v0 = r0 < M, v1 = r1 < M;
    float C[8][4] = {};
    for (int c = 0; c < nch; c++) {
        unsigned a[4][4];
        load_A_chunk(a, A, lda, r0, r1, v0, v1, c * 32, qc);
        mma_gate(C, a, Bpk + (size_t)c * 2048, lane);
    }
#pragma unroll
    for (int f = 0; f < 8; f++) {
        int col = 8 * f + 2 * qc;
        if (v0) *(float2*)(out + (size_t)r0 * 64 + col) = make_float2(C[f][0], C[f][1]);
        if (v1) *(float2*)(out + (size_t)r1 * 64 + col) = make_float2(C[f][2], C[f][3]);
    }
}

// ---------------- pre0 (128-row, 3 gates share A) ---------------------------
__global__ __launch_bounds__(256) void k_pre0m(const float* __restrict__ bu,
                                               const float* __restrict__ br,
                                               const float* __restrict__ bc) {
    int tid = threadIdx.x, lane = tid & 31, w = tid >> 5;
    int qr = lane >> 2, qc = lane & 3;
    int r0 = blockIdx.x * 128 + w * 16 + qr, r1 = r0 + 8;   // TN % 128 == 0
    float C[3][8][4] = {};
    for (int ch = 0; ch < 3; ch++) {
        const float* S = ch ? g_g0all : g_xt;
        int lda = ch ? 64 : 32;
        int k0 = (ch == 2) ? 32 : 0;
        unsigned a[4][4];
        load_A_chunk(a, S, lda, r0, r1, true, true, k0, qc);
#pragma unroll
        for (int g = 0; g < 3; g++)
            mma_gate(C[g], a, g_pk_pre0 + ((size_t)g * 3 + ch) * 2048, lane);
    }
#pragma unroll
    for (int g = 0; g < 3; g++) {
        const float* b = (g == 0) ? bu : (g == 1) ? br : bc;
#pragma unroll
        for (int f = 0; f < 8; f++) {
            int col = 8 * f + 2 * qc;
            float2 b2 = *(const float2*)(b + col);
            *(float2*)(g_p0all + (size_t)r0 * 192 + g * 64 + col) =
                make_float2(C[g][f][0] + b2.x, C[g][f][1] + b2.y);
            *(float2*)(g_p0all + (size_t)r1 * 192 + g * 64 + col) =
                make_float2(C[g][f][2] + b2.x, C[g][f][3] + b2.y);
        }
    }
}

// ---------------- qkv (128-row) ----------------------------------------------
__global__ __launch_bounds__(256) void k_qkvm(const float* __restrict__ ipb) {
    int tid = threadIdx.x, lane = tid & 31, w = tid >> 5;
    int qr = lane >> 2, qc = lane & 3;
    int r0 = blockIdx.x * 128 + w * 16 + qr, r1 = r0 + 8;
    float C[3][8][4] = {};
    for (int ch = 0; ch < 2; ch++) {
        unsigned a[4][4];
        load_A_chunk(a, g_hseq, 64, r0, r1, true, true, ch * 32, qc);
#pragma unroll
        for (int g = 0; g < 3; g++)
            mma_gate(C[g], a, g_pk_qkv + ((size_t)g * 2 + ch) * 2048, lane);
    }
#pragma unroll
    for (int g = 0; g < 3; g++) {
#pragma unroll
        for (int f = 0; f < 8; f++) {
            int col = 8 * f + 2 * qc;
            float2 b2 = *(const float2*)(ipb + g * 64 + col);
            *(float2*)(g_qkv + (size_t)r0 * 192 + g * 64 + col) =
                make_float2(C[g][f][0] + b2.x, C[g][f][1] + b2.y);
            *(float2*)(g_qkv + (size_t)r1 * 192 + g * 64 + col) =
                make_float2(C[g][f][2] + b2.x, C[g][f][3] + b2.y);
        }
    }
}

// ---------------- layer0 GCN agg over all t (fp32) ---------------------------
__global__ void k_agg_all(const float* __restrict__ bg) {
    int gw = blockIdx.x * (blockDim.x >> 5) + (threadIdx.x >> 5);
    if (gw >= TN) return;
    int t = gw / Nn, n = gw - t * Nn;
    int lane = threadIdx.x & 31;
    const float* xw = g_xw0all + (size_t)t * Nn * Hh;
    int beg = g_rowptr[n], end = g_rowptr[n + 1];
    float a0 = 0.f, a1 = 0.f;
#pragma unroll 4
    for (int p = beg; p < end; p++) {
        int s = g_csrsrc[p];
        float nm = g_csrnorm[p];
        a0 += nm * xw[(size_t)s * Hh + lane];
        a1 += nm * xw[(size_t)s * Hh + lane + 32];
    }
    float dv = g_dinv[n];
    float dd = dv * dv;
    a0 += dd * xw[(size_t)n * Hh + lane] + bg[lane];
    a1 += dd * xw[(size_t)n * Hh + lane + 32] + bg[lane + 32];
    g_g0all[(size_t)gw * Hh + lane] = sigmoidf_(a0);
    g_g0all[(size_t)gw * Hh + lane + 32] = sigmoidf_(a1);
}

// ---------------- layer0 urc + GRU update + xw=h@Wg1 (fused) -----------------
__global__ __launch_bounds__(256) void k_urc0x(const float* __restrict__ p0,
                                               float* __restrict__ h,
                                               float* __restrict__ xw) {
    __shared__ unsigned U[64 * 136];     // [k][row] tf32 (single index space, warp-disjoint)
    int tid = threadIdx.x, lane = tid & 31, w = tid >> 5;
    int qr = lane >> 2, qc = lane & 3;
    int rl0 = w * 16 + qr;
    int r0 = blockIdx.x * 128 + rl0, r1 = r0 + 8;
    bool v0 = r0 < Nn, v1 = r1 < Nn;
    float Cu[8][4], Cr[8][4], Cc[8][4];
#pragma unroll
    for (int f = 0; f < 8; f++) {
        int col = 8 * f + 2 * qc;
        float2 z = make_float2(0.f, 0.f);
        float2 u0 = z, u1 = z, rr0 = z, rr1 = z, c0 = z, c1 = z;
        if (v0) {
            u0  = *(const float2*)(p0 + (size_t)r0 * 192 + col);
            rr0 = *(const float2*)(p0 + (size_t)r0 * 192 + 64 + col);
            c0  = *(const float2*)(p0 + (size_t)r0 * 192 + 128 + col);
        }
        if (v1) {
            u1  = *(const float2*)(p0 + (size_t)r1 * 192 + col);
            rr1 = *(const float2*)(p0 + (size_t)r1 * 192 + 64 + col);
            c1  = *(const float2*)(p0 + (size_t)r1 * 192 + 128 + col);
        }
        Cu[f][0] = u0.x;  Cu[f][1] = u0.y;  Cu[f][2] = u1.x;  Cu[f][3] = u1.y;
        Cr[f][0] = rr0.x; Cr[f][1] = rr0.y; Cr[f][2] = rr1.x; Cr[f][3] = rr1.y;
        Cc[f][0] = c0.x;  Cc[f][1] = c0.y;  Cc[f][2] = c1.x;  Cc[f][3] = c1.y;
    }
    for (int ch = 0; ch < 2; ch++) {
        unsigned a[4][4];
        load_A_chunk(a, h, 64, r0, r1, v0, v1, ch * 32, qc);
        mma_gate(Cu, a, g_pk_urc0 + (size_t)(0 + ch) * 2048, lane);
        mma_gate(Cr, a, g_pk_urc0 + (size_t)(2 + ch) * 2048, lane);
    }
    // epilogue1: u=sig, U=tf32(sig(r)*h), stash h in Cr
#pragma unroll
    for (int f = 0; f < 8; f++) {
        int col = 8 * f + 2 * qc;
#pragma unroll
        for (int half = 0; half < 2; half++) {
            int rl = rl0 + 8 * half;
            int row = blockIdx.x * 128 + rl;
            float u0 = sigmoidf_(Cu[f][2 * half + 0]);
            float u1 = sigmoidf_(Cu[f][2 * half + 1]);
            float rg0 = sigmoidf_(Cr[f][2 * half + 0]);
            float rg1 = sigmoidf_(Cr[f][2 * half + 1]);
            Cu[f][2 * half + 0] = u0;
            Cu[f][2 * half + 1] = u1;
            float2 hv = make_float2(0.f, 0.f);
            if (row < Nn) hv = *(const float2*)(h + (size_t)row * 64 + col);
            Cr[f][2 * half + 0] = hv.x;
            Cr[f][2 * half + 1] = hv.y;
            U[col * 136 + rl] = f2tf32(rg0 * hv.x);
            U[(col + 1) * 136 + rl] = f2tf32(rg1 * hv.y);
        }
    }
    __syncwarp();
    for (int ch = 0; ch < 2; ch++) {
        unsigned a[4][4];
        load_A_smemU(a, U, rl0, ch * 32, qc);
        mma_gate(Cc, a, g_pk_urc0 + (size_t)(4 + ch) * 2048, lane);
    }
    // epilogue2: h_new; store h; stage h_new into U for xw pass
#pragma unroll
    for (int f = 0; f < 8; f++) {
        int col = 8 * f + 2 * qc;
#pragma unroll
        for (int half = 0; half < 2; half++) {
            int rl = rl0 + 8 * half;
            int row = blockIdx.x * 128 + rl;
            float hv0 = Cr[f][2 * half + 0], hv1 = Cr[f][2 * half + 1];
            float c0 = tanhf(Cc[f][2 * half + 0]);
            float c1 = tanhf(Cc[f][2 * half + 1]);
            float u0 = Cu[f][2 * half + 0], u1 = Cu[f][2 * half + 1];
            float o0 = u0 * hv0 + (1.f - u0) * c0;
            float o1 = u1 * hv1 + (1.f - u1) * c1;
            if (row < Nn) *(float2*)(h + (size_t)row * 64 + col) = make_float2(o0, o1);
            U[col * 136 + rl] = f2tf32(o0);
            U[(col + 1) * 136 + rl] = f2tf32(o1);
        }
    }
    __syncwarp();
    // xw = h_new @ Wg1
    float Cx[8][4] = {};
    for (int ch = 0; ch < 2; ch++) {
        unsigned a[4][4];
        load_A_smemU(a, U, rl0, ch * 32, qc);
        mma_gate(Cx, a, g_pk_Wg1 + (size_t)ch * 2048, lane);
    }
#pragma unroll
    for (int f = 0; f < 8; f++) {
        int col = 8 * f + 2 * qc;
        if (v0) *(float2*)(xw + (size_t)r0 * 64 + col) = make_float2(Cx[f][0], Cx[f][1]);
        if (v1) *(float2*)(xw + (size_t)r1 * 64 + col) = make_float2(Cx[f][2], Cx[f][3]);
    }
}

// ---------------- layer1: fused GCN gather + urc + GRU update ----------------
__global__ __launch_bounds__(256) void k_urc1f(
    const float* __restrict__ h0,
    const float* __restrict__ bu, const float* __restrict__ br,
    const float* __restrict__ bc, const float* __restrict__ bg,
    float* __restrict__ h, float* __restrict__ hseq) {
    __shared__ float SB[64 * 136];       // phase A: G[row][68] floats; AFTER BARRIER: U[k][136] tf32
    float* G = SB;
    unsigned* U = (unsigned*)SB;
    int tid = threadIdx.x, lane = tid & 31, w = tid >> 5;
    int qr = lane >> 2, qc = lane & 3;
    int rl0 = w * 16 + qr;
    int r0 = blockIdx.x * 128 + rl0, r1 = r0 + 8;
    bool v0 = r0 < Nn, v1 = r1 < Nn;

    // ---- phase A: gather gg for own 128 rows (warp w -> rows w*16..+15) ----
    float bg0v = bg[lane], bg1v = bg[lane + 32];
    for (int i = 0; i < 16; i++) {
        int rl = w * 16 + i;
        int n = blockIdx.x * 128 + rl;
        float a0 = 0.f, a1 = 0.f;
        if (n < Nn) {
            int beg = g_rowptr[n], end = g_rowptr[n + 1];
#pragma unroll 4
            for (int p = beg; p < end; p++) {
                int s = g_csrsrc[p];
                float nm = g_csrnorm[p];
                a0 += nm * g_xw[(size_t)s * Hh + lane];
                a1 += nm * g_xw[(size_t)s * Hh + lane + 32];
            }
            float dv = g_dinv[n];
            float dd = dv * dv;
            a0 = sigmoidf_(a0 + dd * g_xw[(size_t)n * Hh + lane] + bg0v);
            a1 = sigmoidf_(a1 + dd * g_xw[(size_t)n * Hh + lane + 32] + bg1v);
        }
        G[rl * 68 + lane] = a0;
        G[rl * 68 + lane + 32] = a1;
    }
    __syncwarp();

    // ---- phase B: pass1 MMAs over [h0 | g | h] ----
    float Cu[8][4] = {}, Cr[8][4] = {}, Cc[8][4] = {};
    for (int ch = 0; ch < 6; ch++) {
        unsigned a[4][4];
        if (ch < 2)       load_A_chunk(a, h0, 64, r0, r1, v0, v1, (ch & 1) * 32, qc);
        else if (ch < 4)  load_A_smemF(a, G, rl0, (ch & 1) * 32, qc);
        else              load_A_chunk(a, h, 64, r0, r1, v0, v1, (ch & 1) * 32, qc);
        mma_gate(Cu, a, g_pk_urc1 + (size_t)ch * 2048, lane);
        mma_gate(Cr, a, g_pk_urc1 + (size_t)(6 + ch) * 2048, lane);
        if (ch < 4) mma_gate(Cc, a, g_pk_urc1 + (size_t)(12 + ch) * 2048, lane);
    }
    // FIX R7: G (row-major) and U (col-major) alias with OVERLAPPING raw addresses
    // across warps. A fast warp's U writes below would clobber a slow warp's G
    // reads above. Block barrier required between last G read and first U write.
    __syncthreads();
    // epilogue1
#pragma unroll
    for (int f = 0; f < 8; f++) {
        int col = 8 * f + 2 * qc;
        float2 bu2 = *(const float2*)(bu + col);
        float2 br2 = *(const float2*)(br + col);
#pragma unroll
        for (int half = 0; half < 2; half++) {
            int rl = rl0 + 8 * half;
            int row = blockIdx.x * 128 + rl;
            float u0 = sigmoidf_(Cu[f][2 * half + 0] + bu2.x);
            float u1 = sigmoidf_(Cu[f][2 * half + 1] + bu2.y);
            float rg0 = sigmoidf_(Cr[f][2 * half + 0] + br2.x);
            float rg1 = sigmoidf_(Cr[f][2 * half + 1] + br2.y);
            Cu[f][2 * half + 0] = u0;
            Cu[f][2 * half + 1] = u1;
            float2 hv = make_float2(0.f, 0.f);
            if (row < Nn) hv = *(const float2*)(h + (size_t)row * 64 + col);
            Cr[f][2 * half + 0] = hv.x;
            Cr[f][2 * half + 1] = hv.y;
            U[col * 136 + rl] = f2tf32(rg0 * hv.x);
            U[(col + 1) * 136 + rl] = f2tf32(rg1 * hv.y);
        }
    }
    __syncwarp();
    for (int ch = 0; ch < 2; ch++) {
        unsigned a[4][4];
        load_A_smemU(a, U, rl0, ch * 32, qc);
        mma_gate(Cc, a, g_pk_urc1 + (size_t)(16 + ch) * 2048, lane);
    }
#pragma unroll
    for (int f = 0; f < 8; f++) {
        int col = 8 * f + 2 * qc;
        float2 bc2 = *(const float2*)(bc + col);
#pragma unroll
        for (int half = 0; half < 2; half++) {
            int row = blockIdx.x * 128 + rl0 + 8 * half;
            if (row >= Nn) continue;
            float hv0 = Cr[f][2 * half + 0], hv1 = Cr[f][2 * half + 1];
            float c0 = tanhf(Cc[f][2 * half + 0] + bc2.x);
            float c1 = tanhf(Cc[f][2 * half + 1] + bc2.y);
            float u0 = Cu[f][2 * half + 0], u1 = Cu[f][2 * half + 1];
            float2 o = make_float2(u0 * hv0 + (1.f - u0) * c0,
                                   u1 * hv1 + (1.f - u1) * c1);
            *(float2*)(h + (size_t)row * 64 + col) = o;
            *(float2*)(hseq + (size_t)row * 64 + col) = o;
        }
    }
}

// ---------------- attention tail -------------------------------------------
__global__ __launch_bounds__(128) void k_attn2(
    const float* __restrict__ opb,
    const float* __restrict__ ow, const float* __restrict__ ob,
    float* __restrict__ out) {
    __shared__ float s_qkv[4][Tt * 192];
    __shared__ float s_sc[4][2 * Tt * Tt];
    __shared__ float s_cs[4][2 * Tt];
    __shared__ float s_ob[4][Hh];
    __shared__ float s_ha[4][Hh];
    int w = threadIdx.x >> 5, lane = threadIdx.x & 31;
    int n = blockIdx.x * 4 + w;
    if (n >= Nn) return;
    float* qkv = s_qkv[w];
    float* sc = s_sc[w];
    float* cs = s_cs[w];
    float* obw = s_ob[w];
    float* haw = s_ha[w];

    for (int i = lane; i < Tt * 48; i += 32) {
        int t = i / 48, r = i % 48;
        *(float4*)&qkv[t * 192 + r * 4] =
            *(const float4*)&g_qkv[((size_t)t * Nn + n) * 192 + r * 4];
    }
    __syncwarp();
    for (int idx = lane; idx < 2 * Tt * Tt; idx += 32) {
        int hd = idx / (Tt * Tt);
        int r = idx % (Tt * Tt);
        int t = r / Tt, s = r % Tt;
        const float* qp = &qkv[t * 192 + hd * 32];
        const float* kp = &qkv[s * 192 + 64 + hd * 32];
        float a = 0.f;
#pragma unroll
        for (int d = 0; d < 32; d++) a += qp[d] * kp[d];
        sc[idx] = a * 0.17677669529663687f;
    }
    __syncwarp();
    if (lane < 2 * Tt) {
        float* row = &sc[lane * Tt];
        float mx = row[0];
#pragma unroll
        for (int s = 1; s < Tt; s++) mx = fmaxf(mx, row[s]);
        float sum = 0.f;
#pragma unroll
        for (int s = 0; s < Tt; s++) { float e = __expf(row[s] - mx); row[s] = e; sum += e; }
        float inv = 1.0f / sum;
#pragma unroll
        for (int s = 0; s < Tt; s++) row[s] *= inv;
    }
    __syncwarp();
    if (lane < 2 * Tt) {
        int hd = lane / Tt, s = lane % Tt;
        float a = 0.f;
#pragma unroll
        for (int t = 0; t < Tt; t++) a += sc[hd * Tt * Tt + t * Tt + s];
        cs[lane] = a * (1.0f / 12.0f);
    }
    __syncwarp();
    for (int m = 0; m < 2; m++) {
        int j = lane + 32 * m;
        int hd = j >> 5;
        float a = 0.f;
#pragma unroll
        for (int s = 0; s < Tt; s++) a += cs[hd * Tt + s] * qkv[s * 192 + 128 + j];
        obw[j] = a;
    }
    __syncwarp();
    for (int m = 0; m < 2; m++) {
        int i = lane + 32 * m;
        float a = opb[i];
#pragma unroll
        for (int j = 0; j < Hh; j++) a += g_opwT[j * Hh + i] * obw[j];
        haw[i] = a;
    }
    __syncwarp();
    if (lane < OUTD) {
        float a = ob[lane];
#pragma unroll
        for (int i = 0; i < Hh; i++) a += haw[i] * ow[(size_t)i * OUTD + lane];
        out[(size_t)n * OUTD + lane] = a;
    }
}

// ---------------- host ----------------
extern "C" void kernel_launch(void* const* d_in, const int* in_sizes, int n_in,
                              void* d_out, int out_size) {
    (void)in_sizes; (void)n_in; (void)out_size;
    const float* x   = (const float*)d_in[0];
    const int*   ei  = (const int*)d_in[1];
    const float* ea  = (const float*)d_in[2];
    const float* Wg0 = (const float*)d_in[3];
    const float* bg0 = (const float*)d_in[4];
    const float* Wu0 = (const float*)d_in[5];
    const float* bu0 = (const float*)d_in[6];
    const float* Wr0 = (const float*)d_in[7];
    const float* br0 = (const float*)d_in[8];
    const float* Wc0 = (const float*)d_in[9];
    const float* bc0 = (const float*)d_in[10];
    const float* Wg1 = (const float*)d_in[11];
    const float* bg1 = (const float*)d_in[12];
    const float* Wu1 = (const float*)d_in[13];
    const float* bu1 = (const float*)d_in[14];
    const float* Wr1 = (const float*)d_in[15];
    const float* br1 = (const float*)d_in[16];
    const float* Wc1 = (const float*)d_in[17];
    const float* bc1 = (const float*)d_in[18];
    const float* ipw = (const float*)d_in[19];
    const float* ipb = (const float*)d_in[20];
    const float* opw = (const float*)d_in[21];
    const float* opb = (const float*)d_in[22];
    const float* ow  = (const float*)d_in[23];
    const float* ob  = (const float*)d_in[24];
    float* out = (float*)d_out;

    void *p_deg, *p_cnt, *p_cur, *p_h0, *p_h1, *p_xt, *p_hseq, *p_xw0all, *p_p0all, *p_xw;
    void *p_ipwT, *p_pkWg0, *p_pkpre0, *p_pkurc0, *p_pkWg1, *p_pkurc1, *p_pkqkv;
    cudaGetSymbolAddress(&p_deg, g_deg);
    cudaGetSymbolAddress(&p_cnt, g_cnt);
    cudaGetSymbolAddress(&p_cur, g_cur);
    cudaGetSymbolAddress(&p_h0, g_h0);
    cudaGetSymbolAddress(&p_h1, g_h1);
    cudaGetSymbolAddress(&p_xt, g_xt);
    cudaGetSymbolAddress(&p_hseq, g_hseq);
    cudaGetSymbolAddress(&p_xw0all, g_xw0all);
    cudaGetSymbolAddress(&p_p0all, g_p0all);
    cudaGetSymbolAddress(&p_xw, g_xw);
    cudaGetSymbolAddress(&p_ipwT, g_ipwT);
    cudaGetSymbolAddress(&p_pkWg0, g_pk_Wg0);
    cudaGetSymbolAddress(&p_pkpre0, g_pk_pre0);
    cudaGetSymbolAddress(&p_pkurc0, g_pk_urc0);
    cudaGetSymbolAddress(&p_pkWg1, g_pk_Wg1);
    cudaGetSymbolAddress(&p_pkurc1, g_pk_urc1);
    cudaGetSymbolAddress(&p_pkqkv, g_pk_qkv);

    cudaMemsetAsync(p_deg, 0, Nn * sizeof(float), 0);
    cudaMemsetAsync(p_cnt, 0, Nn * sizeof(int), 0);
    cudaMemsetAsync(p_cur, 0, Nn * sizeof(int), 0);
    cudaMemsetAsync(p_h0, 0, (size_t)Nn * Hh * sizeof(float), 0);
    cudaMemsetAsync(p_h1, 0, (size_t)Nn * Hh * sizeof(float), 0);

    k_transpose<<<(Nn * Ff * Tt + 255) / 256, 256>>>(x);
    k_trW<<<(192 * Hh + 255) / 256, 256>>>(ipw, opw);
    k_deg_hist<<<(Ee + 255) / 256, 256>>>(ei, ea);
    k_dinv<<<(Nn + 255) / 256, 256>>>();
    k_norm<<<(Ee + 255) / 256, 256>>>(ei, ea);
    k_scan<<<1, 1024>>>();
    k_fill<<<(Ee + 255) / 256, 256>>>(ei);

    unsigned* pkWg0  = (unsigned*)p_pkWg0;
    unsigned* pkpre0 = (unsigned*)p_pkpre0;
    unsigned* pkurc0 = (unsigned*)p_pkurc0;
    unsigned* pkWg1  = (unsigned*)p_pkWg1;
    unsigned* pkurc1 = (unsigned*)p_pkurc1;
    unsigned* pkqkv  = (unsigned*)p_pkqkv;
    float* ipwT = (float*)p_ipwT;
    k_pack<<<4, 128>>>(Wg0, 64, 1, pkWg0);
    k_pack<<<12, 128>>>(Wu0, 64, 3, pkpre0 + 0 * 2048);
    k_pack<<<12, 128>>>(Wr0, 64, 3, pkpre0 + 3 * 2048);
    k_pack<<<12, 128>>>(Wc0, 64, 3, pkpre0 + 6 * 2048);
    k_pack<<<8, 128>>>(Wu0 + 96 * Hh, 64, 2, pkurc0 + 0 * 2048);
    k_pack<<<8, 128>>>(Wr0 + 96 * Hh, 64, 2, pkurc0 + 2 * 2048);
    k_pack<<<8, 128>>>(Wc0 + 96 * Hh, 64, 2, pkurc0 + 4 * 2048);
    k_pack<<<8, 128>>>(Wg1, 64, 2, pkWg1);
    k_pack<<<24, 128>>>(Wu1, 64, 6, pkurc1 + 0 * 2048);
    k_pack<<<24, 128>>>(Wr1, 64, 6, pkurc1 + 6 * 2048);
    k_pack<<<24, 128>>>(Wc1, 64, 6, pkurc1 + 12 * 2048);
    k_pack<<<8, 128>>>(ipwT + 0,   192, 2, pkqkv + 0 * 2048);
    k_pack<<<8, 128>>>(ipwT + 64,  192, 2, pkqkv + 2 * 2048);
    k_pack<<<8, 128>>>(ipwT + 128, 192, 2, pkqkv + 4 * 2048);

    // ---- hoisted precomputes ----
    k_mma_g<<<TN / 128, 256>>>((const float*)p_xt, Ff, 1, TN, pkWg0, (float*)p_xw0all);
    k_agg_all<<<(TN + 7) / 8, 256>>>(bg0);
    k_pre0m<<<TN / 128, 256>>>(bu0, br0, bc0);

    const int GB = (Nn + 127) / 128;          // 157
    float* h0 = (float*)p_h0;
    float* h1 = (float*)p_h1;

    for (int t = 0; t < Tt; t++) {
        k_urc0x<<<GB, 256>>>((const float*)p_p0all + (size_t)t * Nn * 192, h0, (float*)p_xw);
        k_urc1f<<<GB, 256>>>(h0, bu1, br1, bc1, bg1, h1,
                             (float*)p_hseq + (size_t)t * Nn * Hh);
    }

    k_qkvm<<<TN / 128, 256>>>(ipb);
    k_attn2<<<(Nn + 3) / 4, 128>>>(opb, ow, ob, out);
}

// round 8
// speedup vs baseline: 1.2124x; 1.2124x over previous
#include <cuda_runtime.h>
#include <math.h>
#include <stdint.h>

#define Nn 20000
#define Ff 32
#define Tt 12
#define Hh 64
#define Ee 320000
#define OUTD 12
#define TN (Tt * Nn)

// ---------------- scratch ----------------
static __device__ float g_xt[(size_t)TN * Ff];
static __device__ float g_deg[Nn];
static __device__ float g_dinv[Nn];
static __device__ float g_norm[Ee];
static __device__ int   g_cnt[Nn];
static __device__ int   g_cur[Nn];
static __device__ int   g_rowptr[Nn + 1];
static __device__ int   g_csrsrc[Ee];
static __device__ float g_csrnorm[Ee];
static __device__ float g_xw0all[(size_t)TN * Hh];
static __device__ float g_g0all[(size_t)TN * Hh];
static __device__ float g_p0all[(size_t)TN * 192];
static __device__ float g_xw[(size_t)Nn * Hh];
static __device__ float g_gg[(size_t)Nn * Hh];
static __device__ float g_h0[(size_t)Nn * Hh];
static __device__ float g_h1[(size_t)Nn * Hh];
static __device__ float g_hseq[(size_t)TN * Hh];
static __device__ float g_qkv[(size_t)TN * 192];
static __device__ float g_ipwT[Hh * 192];
static __device__ float g_opwT[Hh * Hh];

// pre-packed tf32 b-fragments
static __device__ unsigned g_pk_Wg0[1 * 2048];
static __device__ unsigned g_pk_pre0[9 * 2048];
static __device__ unsigned g_pk_urc0[6 * 2048];
static __device__ unsigned g_pk_Wg1[2 * 2048];
static __device__ unsigned g_pk_urc1[18 * 2048];
static __device__ unsigned g_pk_qkv[6 * 2048];

__device__ __forceinline__ float sigmoidf_(float x) { return 1.0f / (1.0f + __expf(-x)); }

__device__ __forceinline__ unsigned f2tf32(float f) {
    unsigned r;
    asm("cvt.rna.tf32.f32 %0, %1;" : "=r"(r) : "f"(f));
    return r;
}

__device__ __forceinline__ void mma_tf32(float c[4], const unsigned a[4], unsigned b0, unsigned b1) {
    asm volatile(
        "mma.sync.aligned.m16n8k8.row.col.f32.tf32.tf32.f32 "
        "{%0,%1,%2,%3}, {%4,%5,%6,%7}, {%8,%9}, {%0,%1,%2,%3};"
        : "+f"(c[0]), "+f"(c[1]), "+f"(c[2]), "+f"(c[3])
        : "r"(a[0]), "r"(a[1]), "r"(a[2]), "r"(a[3]), "r"(b0), "r"(b1));
}

__device__ __forceinline__ void load_A_chunk(unsigned a[4][4], const float* __restrict__ A,
                                             int lda, int r0, int r1, bool v0, bool v1,
                                             int k0, int qc) {
#pragma unroll
    for (int s = 0; s < 4; s++) {
        int k = k0 + 8 * s + qc;
        float x0 = v0 ? A[(size_t)r0 * lda + k] : 0.f;
        float x1 = v1 ? A[(size_t)r1 * lda + k] : 0.f;
        float x2 = v0 ? A[(size_t)r0 * lda + k + 4] : 0.f;
        float x3 = v1 ? A[(size_t)r1 * lda + k + 4] : 0.f;
        a[s][0] = f2tf32(x0); a[s][1] = f2tf32(x1);
        a[s][2] = f2tf32(x2); a[s][3] = f2tf32(x3);
    }
}

// A chunk from smem tf32 buffer U[k][136]
__device__ __forceinline__ void load_A_smemU(unsigned a[4][4], const unsigned* U,
                                             int rl0, int k0, int qc) {
#pragma unroll
    for (int s = 0; s < 4; s++) {
        int k = k0 + 8 * s + qc;
        a[s][0] = U[k * 136 + rl0];
        a[s][1] = U[k * 136 + rl0 + 8];
        a[s][2] = U[(k + 4) * 136 + rl0];
        a[s][3] = U[(k + 4) * 136 + rl0 + 8];
    }
}

__device__ __forceinline__ void mma_gate(float C[8][4], const unsigned a[4][4],
                                         const unsigned* __restrict__ Bpk, int lane) {
    const uint4* B4 = (const uint4*)Bpk;
#pragma unroll
    for (int s = 0; s < 4; s++)
#pragma unroll
        for (int f2 = 0; f2 < 4; f2++) {
            uint4 b = B4[(s * 4 + f2) * 32 + lane];
            mma_tf32(C[2 * f2], a[s], b.x, b.y);
            mma_tf32(C[2 * f2 + 1], a[s], b.z, b.w);
        }
}

// ---------------- weight pack ----------------
__global__ void k_pack(const float* __restrict__ W, int ldw, int nch,
                       unsigned* __restrict__ dst) {
    int tid = blockIdx.x * blockDim.x + threadIdx.x;
    if (tid >= nch * 512) return;
    int c = tid >> 9, r = tid & 511;
    int s = r >> 7, f2 = (r >> 5) & 3, lane = r & 31;
    int qr = lane >> 2, qc = lane & 3;
    int k1 = c * 32 + 8 * s + qc, k2 = k1 + 4;
    int n1 = 16 * f2 + qr, n2 = n1 + 8;
    uint4 o;
    o.x = f2tf32(W[(size_t)k1 * ldw + n1]);
    o.y = f2tf32(W[(size_t)k2 * ldw + n1]);
    o.z = f2tf32(W[(size_t)k1 * ldw + n2]);
    o.w = f2tf32(W[(size_t)k2 * ldw + n2]);
    ((uint4*)dst)[tid] = o;
}

// ---------------- preprocessing ----------------
__global__ void k_transpose(const float* __restrict__ x) {
    int idx = blockIdx.x * blockDim.x + threadIdx.x;
    if (idx >= Nn * Ff * Tt) return;
    int f = idx & (Ff - 1);
    int t = (idx / Ff) % Tt;
    int n = idx / (Ff * Tt);
    g_xt[(size_t)t * Nn * Ff + (size_t)n * Ff + f] = x[(size_t)n * Ff * Tt + (size_t)f * Tt + t];
}

__global__ void k_trW(const float* __restrict__ ipw, const float* __restrict__ opw) {
    int i = blockIdx.x * blockDim.x + threadIdx.x;
    if (i < 192 * Hh) { int r = i / Hh, c = i % Hh; g_ipwT[c * 192 + r] = ipw[i]; }
    if (i < Hh * Hh)  { int r = i / Hh, c = i % Hh; g_opwT[c * Hh + r] = opw[i]; }
}

__global__ void k_deg_hist(const int* __restrict__ ei, const float* __restrict__ ea) {
    int e = blockIdx.x * blockDim.x + threadIdx.x;
    if (e >= Ee) return;
    int d = ei[Ee + e];
    atomicAdd(&g_deg[d], ea[2 * e + 1]);
    atomicAdd(&g_cnt[d], 1);
}

__global__ void k_dinv() {
    int n = blockIdx.x * blockDim.x + threadIdx.x;
    if (n < Nn) g_dinv[n] = rsqrtf(g_deg[n] + 1.0f);
}

__global__ void k_norm(const int* __restrict__ ei, const float* __restrict__ ea) {
    int e = blockIdx.x * blockDim.x + threadIdx.x;
    if (e >= Ee) return;
    g_norm[e] = g_dinv[ei[e]] * ea[2 * e + 1] * g_dinv[ei[Ee + e]];
}

__global__ void k_scan() {
    __shared__ int sbuf[1024];
    __shared__ int s_carry;
    int tid = threadIdx.x;
    if (tid == 0) { s_carry = 0; g_rowptr[0] = 0; }
    __syncthreads();
    for (int base = 0; base < Nn; base += 1024) {
        int v = (base + tid < Nn) ? g_cnt[base + tid] : 0;
        sbuf[tid] = v;
        __syncthreads();
        for (int off = 1; off < 1024; off <<= 1) {
            int t2 = (tid >= off) ? sbuf[tid - off] : 0;
            __syncthreads();
            sbuf[tid] += t2;
            __syncthreads();
        }
        int incl = sbuf[tid] + s_carry;
        if (base + tid < Nn) g_rowptr[base + tid + 1] = incl;
        int total = sbuf[1023];
        __syncthreads();
        if (tid == 0) s_carry += total;
        __syncthreads();
    }
}

__global__ void k_fill(const int* __restrict__ ei) {
    int e = blockIdx.x * blockDim.x + threadIdx.x;
    if (e >= Ee) return;
    int d = ei[Ee + e];
    int pos = g_rowptr[d] + atomicAdd(&g_cur[d], 1);
    g_csrsrc[pos] = ei[e];
    g_csrnorm[pos] = g_norm[e];
}

// ---------------- generic MMA GEMM (128-row blocks) -------------------------
__global__ __launch_bounds__(256) void k_mma_g(const float* __restrict__ A, int lda,
                                               int nch, int M,
                                               const unsigned* __restrict__ Bpk,
                                               float* __restrict__ out) {
    int tid = threadIdx.x, lane = tid & 31, w = tid >> 5;
    int qr = lane >> 2, qc = lane & 3;
    int r0 = blockIdx.x * 128 + w * 16 + qr, r1 = r0 + 8;
    bool v0 = r0 < M, v1 = r1 < M;
    float C[8][4] = {};
    for (int c = 0; c < nch; c++) {
        unsigned a[4][4];
        load_A_chunk(a, A, lda, r0, r1, v0, v1, c * 32, qc);
        mma_gate(C, a, Bpk + (size_t)c * 2048, lane);
    }
#pragma unroll
    for (int f = 0; f < 8; f++) {
        int col = 8 * f + 2 * qc;
        if (v0) *(float2*)(out + (size_t)r0 * 64 + col) = make_float2(C[f][0], C[f][1]);
        if (v1) *(float2*)(out + (size_t)r1 * 64 + col) = make_float2(C[f][2], C[f][3]);
    }
}

// ---------------- pre0 (128-row, 3 gates share A) ---------------------------
__global__ __launch_bounds__(256) void k_pre0m(const float* __restrict__ bu,
                                               const float* __restrict__ br,
                                               const float* __restrict__ bc) {
    int tid = threadIdx.x, lane = tid & 31, w = tid >> 5;
    int qr = lane >> 2, qc = lane & 3;
    int r0 = blockIdx.x * 128 + w * 16 + qr, r1 = r0 + 8;   // TN % 128 == 0
    float C[3][8][4] = {};
    for (int ch = 0; ch < 3; ch++) {
        const float* S = ch ? g_g0all : g_xt;
        int lda = ch ? 64 : 32;
        int k0 = (ch == 2) ? 32 : 0;
        unsigned a[4][4];
        load_A_chunk(a, S, lda, r0, r1, true, true, k0, qc);
#pragma unroll
        for (int g = 0; g < 3; g++)
            mma_gate(C[g], a, g_pk_pre0 + ((size_t)g * 3 + ch) * 2048, lane);
    }
#pragma unroll
    for (int g = 0; g < 3; g++) {
        const float* b = (g == 0) ? bu : (g == 1) ? br : bc;
#pragma unroll
        for (int f = 0; f < 8; f++) {
            int col = 8 * f + 2 * qc;
            float2 b2 = *(const float2*)(b + col);
            *(float2*)(g_p0all + (size_t)r0 * 192 + g * 64 + col) =
                make_float2(C[g][f][0] + b2.x, C[g][f][1] + b2.y);
            *(float2*)(g_p0all + (size_t)r1 * 192 + g * 64 + col) =
                make_float2(C[g][f][2] + b2.x, C[g][f][3] + b2.y);
        }
    }
}

// ---------------- qkv (128-row) ----------------------------------------------
__global__ __launch_bounds__(256) void k_qkvm(const float* __restrict__ ipb) {
    int tid = threadIdx.x, lane = tid & 31, w = tid >> 5;
    int qr = lane >> 2, qc = lane & 3;
    int r0 = blockIdx.x * 128 + w * 16 + qr, r1 = r0 + 8;
    float C[3][8][4] = {};
    for (int ch = 0; ch < 2; ch++) {
        unsigned a[4][4];
        load_A_chunk(a, g_hseq, 64, r0, r1, true, true, ch * 32, qc);
#pragma unroll
        for (int g = 0; g < 3; g++)
            mma_gate(C[g], a, g_pk_qkv + ((size_t)g * 2 + ch) * 2048, lane);
    }
#pragma unroll
    for (int g = 0; g < 3; g++) {
#pragma unroll
        for (int f = 0; f < 8; f++) {
            int col = 8 * f + 2 * qc;
            float2 b2 = *(const float2*)(ipb + g * 64 + col);
            *(float2*)(g_qkv + (size_t)r0 * 192 + g * 64 + col) =
                make_float2(C[g][f][0] + b2.x, C[g][f][1] + b2.y);
            *(float2*)(g_qkv + (size_t)r1 * 192 + g * 64 + col) =
                make_float2(C[g][f][2] + b2.x, C[g][f][3] + b2.y);
        }
    }
}

// ---------------- layer0 GCN agg over all t (fp32) ---------------------------
__global__ void k_agg_all(const float* __restrict__ bg) {
    int gw = blockIdx.x * (blockDim.x >> 5) + (threadIdx.x >> 5);
    if (gw >= TN) return;
    int t = gw / Nn, n = gw - t * Nn;
    int lane = threadIdx.x & 31;
    const float* xw = g_xw0all + (size_t)t * Nn * Hh;
    int beg = g_rowptr[n], end = g_rowptr[n + 1];
    float a0 = 0.f, a1 = 0.f;
#pragma unroll 4
    for (int p = beg; p < end; p++) {
        int s = g_csrsrc[p];
        float nm = g_csrnorm[p];
        a0 += nm * xw[(size_t)s * Hh + lane];
        a1 += nm * xw[(size_t)s * Hh + lane + 32];
    }
    float dv = g_dinv[n];
    float dd = dv * dv;
    a0 += dd * xw[(size_t)n * Hh + lane] + bg[lane];
    a1 += dd * xw[(size_t)n * Hh + lane + 32] + bg[lane + 32];
    g_g0all[(size_t)gw * Hh + lane] = sigmoidf_(a0);
    g_g0all[(size_t)gw * Hh + lane + 32] = sigmoidf_(a1);
}

// ---------------- per-step GCN agg (layer1, 1 warp/node) ---------------------
__global__ void k_gcn_agg(const float* __restrict__ bg) {
    int n = blockIdx.x * (blockDim.x >> 5) + (threadIdx.x >> 5);
    if (n >= Nn) return;
    int lane = threadIdx.x & 31;
    int beg = g_rowptr[n], end = g_rowptr[n + 1];
    float a0 = 0.f, a1 = 0.f;
#pragma unroll 4
    for (int p = beg; p < end; p++) {
        int s = g_csrsrc[p];
        float nm = g_csrnorm[p];
        a0 += nm * g_xw[(size_t)s * Hh + lane];
        a1 += nm * g_xw[(size_t)s * Hh + lane + 32];
    }
    float dv = g_dinv[n];
    float dd = dv * dv;
    a0 += dd * g_xw[(size_t)n * Hh + lane] + bg[lane];
    a1 += dd * g_xw[(size_t)n * Hh + lane + 32] + bg[lane + 32];
    g_gg[(size_t)n * Hh + lane] = sigmoidf_(a0);
    g_gg[(size_t)n * Hh + lane + 32] = sigmoidf_(a1);
}

// ---------------- layer0 urc + GRU update + xw=h@Wg1 (fused) -----------------
__global__ __launch_bounds__(256) void k_urc0x(const float* __restrict__ p0,
                                               float* __restrict__ h,
                                               float* __restrict__ xw) {
    __shared__ unsigned U[64 * 136];     // [k][row] tf32 (single index space, warp-disjoint)
    int tid = threadIdx.x, lane = tid & 31, w = tid >> 5;
    int qr = lane >> 2, qc = lane & 3;
    int rl0 = w * 16 + qr;
    int r0 = blockIdx.x * 128 + rl0, r1 = r0 + 8;
    bool v0 = r0 < Nn, v1 = r1 < Nn;
    float Cu[8][4], Cr[8][4], Cc[8][4];
#pragma unroll
    for (int f = 0; f < 8; f++) {
        int col = 8 * f + 2 * qc;
        float2 z = make_float2(0.f, 0.f);
        float2 u0 = z, u1 = z, rr0 = z, rr1 = z, c0 = z, c1 = z;
        if (v0) {
            u0  = *(const float2*)(p0 + (size_t)r0 * 192 + col);
            rr0 = *(const float2*)(p0 + (size_t)r0 * 192 + 64 + col);
            c0  = *(const float2*)(p0 + (size_t)r0 * 192 + 128 + col);
        }
        if (v1) {
            u1  = *(const float2*)(p0 + (size_t)r1 * 192 + col);
            rr1 = *(const float2*)(p0 + (size_t)r1 * 192 + 64 + col);
            c1  = *(const float2*)(p0 + (size_t)r1 * 192 + 128 + col);
        }
        Cu[f][0] = u0.x;  Cu[f][1] = u0.y;  Cu[f][2] = u1.x;  Cu[f][3] = u1.y;
        Cr[f][0] = rr0.x; Cr[f][1] = rr0.y; Cr[f][2] = rr1.x; Cr[f][3] = rr1.y;
        Cc[f][0] = c0.x;  Cc[f][1] = c0.y;  Cc[f][2] = c1.x;  Cc[f][3] = c1.y;
    }
    for (int ch = 0; ch < 2; ch++) {
        unsigned a[4][4];
        load_A_chunk(a, h, 64, r0, r1, v0, v1, ch * 32, qc);
        mma_gate(Cu, a, g_pk_urc0 + (size_t)(0 + ch) * 2048, lane);
        mma_gate(Cr, a, g_pk_urc0 + (size_t)(2 + ch) * 2048, lane);
    }
    // epilogue1: u=sig, U=tf32(sig(r)*h), stash h in Cr
#pragma unroll
    for (int f = 0; f < 8; f++) {
        int col = 8 * f + 2 * qc;
#pragma unroll
        for (int half = 0; half < 2; half++) {
            int rl = rl0 + 8 * half;
            int row = blockIdx.x * 128 + rl;
            float u0 = sigmoidf_(Cu[f][2 * half + 0]);
            float u1 = sigmoidf_(Cu[f][2 * half + 1]);
            float rg0 = sigmoidf_(Cr[f][2 * half + 0]);
            float rg1 = sigmoidf_(Cr[f][2 * half + 1]);
            Cu[f][2 * half + 0] = u0;
            Cu[f][2 * half + 1] = u1;
            float2 hv = make_float2(0.f, 0.f);
            if (row < Nn) hv = *(const float2*)(h + (size_t)row * 64 + col);
            Cr[f][2 * half + 0] = hv.x;
            Cr[f][2 * half + 1] = hv.y;
            U[col * 136 + rl] = f2tf32(rg0 * hv.x);
            U[(col + 1) * 136 + rl] = f2tf32(rg1 * hv.y);
        }
    }
    __syncwarp();
    for (int ch = 0; ch < 2; ch++) {
        unsigned a[4][4];
        load_A_smemU(a, U, rl0, ch * 32, qc);
        mma_gate(Cc, a, g_pk_urc0 + (size_t)(4 + ch) * 2048, lane);
    }
    // epilogue2: h_new; store h; stage h_new into U for xw pass
#pragma unroll
    for (int f = 0; f < 8; f++) {
        int col = 8 * f + 2 * qc;
#pragma unroll
        for (int half = 0; half < 2; half++) {
            int rl = rl0 + 8 * half;
            int row = blockIdx.x * 128 + rl;
            float hv0 = Cr[f][2 * half + 0], hv1 = Cr[f][2 * half + 1];
            float c0 = tanhf(Cc[f][2 * half + 0]);
            float c1 = tanhf(Cc[f][2 * half + 1]);
            float u0 = Cu[f][2 * half + 0], u1 = Cu[f][2 * half + 1];
            float o0 = u0 * hv0 + (1.f - u0) * c0;
            float o1 = u1 * hv1 + (1.f - u1) * c1;
            if (row < Nn) *(float2*)(h + (size_t)row * 64 + col) = make_float2(o0, o1);
            U[col * 136 + rl] = f2tf32(o0);
            U[(col + 1) * 136 + rl] = f2tf32(o1);
        }
    }
    __syncwarp();
    // xw = h_new @ Wg1
    float Cx[8][4] = {};
    for (int ch = 0; ch < 2; ch++) {
        unsigned a[4][4];
        load_A_smemU(a, U, rl0, ch * 32, qc);
        mma_gate(Cx, a, g_pk_Wg1 + (size_t)ch * 2048, lane);
    }
#pragma unroll
    for (int f = 0; f < 8; f++) {
        int col = 8 * f + 2 * qc;
        if (v0) *(float2*)(xw + (size_t)r0 * 64 + col) = make_float2(Cx[f][0], Cx[f][1]);
        if (v1) *(float2*)(xw + (size_t)r1 * 64 + col) = make_float2(Cx[f][2], Cx[f][3]);
    }
}

// ---------------- layer1 urc + GRU update (K=192, g from global) -------------
__global__ __launch_bounds__(256) void k_urc1m(
    const float* __restrict__ h0,
    const float* __restrict__ bu, const float* __restrict__ br,
    const float* __restrict__ bc,
    float* __restrict__ h, float* __restrict__ hseq) {
    __shared__ unsigned U[64 * 136];     // single index space, warp-disjoint
    int tid = threadIdx.x, lane = tid & 31, w = tid >> 5;
    int qr = lane >> 2, qc = lane & 3;
    int rl0 = w * 16 + qr;
    int r0 = blockIdx.x * 128 + rl0, r1 = r0 + 8;
    bool v0 = r0 < Nn, v1 = r1 < Nn;
    float Cu[8][4] = {}, Cr[8][4] = {}, Cc[8][4] = {};
    for (int ch = 0; ch < 6; ch++) {
        const float* S = (ch < 2) ? h0 : (ch < 4) ? g_gg : h;
        unsigned a[4][4];
        load_A_chunk(a, S, 64, r0, r1, v0, v1, (ch & 1) * 32, qc);
        mma_gate(Cu, a, g_pk_urc1 + (size_t)ch * 2048, lane);
        mma_gate(Cr, a, g_pk_urc1 + (size_t)(6 + ch) * 2048, lane);
        if (ch < 4) mma_gate(Cc, a, g_pk_urc1 + (size_t)(12 + ch) * 2048, lane);
    }
    // epilogue1
#pragma unroll
    for (int f = 0; f < 8; f++) {
        int col = 8 * f + 2 * qc;
        float2 bu2 = *(const float2*)(bu + col);
        float2 br2 = *(const float2*)(br + col);
#pragma unroll
        for (int half = 0; half < 2; half++) {
            int rl = rl0 + 8 * half;
            int row = blockIdx.x * 128 + rl;
            float u0 = sigmoidf_(Cu[f][2 * half + 0] + bu2.x);
            float u1 = sigmoidf_(Cu[f][2 * half + 1] + bu2.y);
            float rg0 = sigmoidf_(Cr[f][2 * half + 0] + br2.x);
            float rg1 = sigmoidf_(Cr[f][2 * half + 1] + br2.y);
            Cu[f][2 * half + 0] = u0;
            Cu[f][2 * half + 1] = u1;
            float2 hv = make_float2(0.f, 0.f);
            if (row < Nn) hv = *(const float2*)(h + (size_t)row * 64 + col);
            Cr[f][2 * half + 0] = hv.x;
            Cr[f][2 * half + 1] = hv.y;
            U[col * 136 + rl] = f2tf32(rg0 * hv.x);
            U[(col + 1) * 136 + rl] = f2tf32(rg1 * hv.y);
        }
    }
    __syncwarp();
    for (int ch = 0; ch < 2; ch++) {
        unsigned a[4][4];
        load_A_smemU(a, U, rl0, ch * 32, qc);
        mma_gate(Cc, a, g_pk_urc1 + (size_t)(16 + ch) * 2048, lane);
    }
#pragma unroll
    for (int f = 0; f < 8; f++) {
        int col = 8 * f + 2 * qc;
        float2 bc2 = *(const float2*)(bc + col);
#pragma unroll
        for (int half = 0; half < 2; half++) {
            int row = blockIdx.x * 128 + rl0 + 8 * half;
            if (row >= Nn) continue;
            float hv0 = Cr[f][2 * half + 0], hv1 = Cr[f][2 * half + 1];
            float c0 = tanhf(Cc[f][2 * half + 0] + bc2.x);
            float c1 = tanhf(Cc[f][2 * half + 1] + bc2.y);
            float u0 = Cu[f][2 * half + 0], u1 = Cu[f][2 * half + 1];
            float2 o = make_float2(u0 * hv0 + (1.f - u0) * c0,
                                   u1 * hv1 + (1.f - u1) * c1);
            *(float2*)(h + (size_t)row * 64 + col) = o;
            *(float2*)(hseq + (size_t)row * 64 + col) = o;
        }
    }
}

// ---------------- attention tail -------------------------------------------
__global__ __launch_bounds__(128) void k_attn2(
    const float* __restrict__ opb,
    const float* __restrict__ ow, const float* __restrict__ ob,
    float* __restrict__ out) {
    __shared__ float s_qkv[4][Tt * 192];
    __shared__ float s_sc[4][2 * Tt * Tt];
    __shared__ float s_cs[4][2 * Tt];
    __shared__ float s_ob[4][Hh];
    __shared__ float s_ha[4][Hh];
    int w = threadIdx.x >> 5, lane = threadIdx.x & 31;
    int n = blockIdx.x * 4 + w;
    if (n >= Nn) return;
    float* qkv = s_qkv[w];
    float* sc = s_sc[w];
    float* cs = s_cs[w];
    float* obw = s_ob[w];
    float* haw = s_ha[w];

    for (int i = lane; i < Tt * 48; i += 32) {
        int t = i / 48, r = i % 48;
        *(float4*)&qkv[t * 192 + r * 4] =
            *(const float4*)&g_qkv[((size_t)t * Nn + n) * 192 + r * 4];
    }
    __syncwarp();
    for (int idx = lane; idx < 2 * Tt * Tt; idx += 32) {
        int hd = idx / (Tt * Tt);
        int r = idx % (Tt * Tt);
        int t = r / Tt, s = r % Tt;
        const float* qp = &qkv[t * 192 + hd * 32];
        const float* kp = &qkv[s * 192 + 64 + hd * 32];
        float a = 0.f;
#pragma unroll
        for (int d = 0; d < 32; d++) a += qp[d] * kp[d];
        sc[idx] = a * 0.17677669529663687f;
    }
    __syncwarp();
    if (lane < 2 * Tt) {
        float* row = &sc[lane * Tt];
        float mx = row[0];
#pragma unroll
        for (int s = 1; s < Tt; s++) mx = fmaxf(mx, row[s]);
        float sum = 0.f;
#pragma unroll
        for (int s = 0; s < Tt; s++) { float e = __expf(row[s] - mx); row[s] = e; sum += e; }
        float inv = 1.0f / sum;
#pragma unroll
        for (int s = 0; s < Tt; s++) row[s] *= inv;
    }
    __syncwarp();
    if (lane < 2 * Tt) {
        int hd = lane / Tt, s = lane % Tt;
        float a = 0.f;
#pragma unroll
        for (int t = 0; t < Tt; t++) a += sc[hd * Tt * Tt + t * Tt + s];
        cs[lane] = a * (1.0f / 12.0f);
    }
    __syncwarp();
    for (int m = 0; m < 2; m++) {
        int j = lane + 32 * m;
        int hd = j >> 5;
        float a = 0.f;
#pragma unroll
        for (int s = 0; s < Tt; s++) a += cs[hd * Tt + s] * qkv[s * 192 + 128 + j];
        obw[j] = a;
    }
    __syncwarp();
    for (int m = 0; m < 2; m++) {
        int i = lane + 32 * m;
        float a = opb[i];
#pragma unroll
        for (int j = 0; j < Hh; j++) a += g_opwT[j * Hh + i] * obw[j];
        haw[i] = a;
    }
    __syncwarp();
    if (lane < OUTD) {
        float a = ob[lane];
#pragma unroll
        for (int i = 0; i < Hh; i++) a += haw[i] * ow[(size_t)i * OUTD + lane];
        out[(size_t)n * OUTD + lane] = a;
    }
}

// ---------------- host ----------------
extern "C" void kernel_launch(void* const* d_in, const int* in_sizes, int n_in,
                              void* d_out, int out_size) {
    (void)in_sizes; (void)n_in; (void)out_size;
    const float* x   = (const float*)d_in[0];
    const int*   ei  = (const int*)d_in[1];
    const float* ea  = (const float*)d_in[2];
    const float* Wg0 = (const float*)d_in[3];
    const float* bg0 = (const float*)d_in[4];
    const float* Wu0 = (const float*)d_in[5];
    const float* bu0 = (const float*)d_in[6];
    const float* Wr0 = (const float*)d_in[7];
    const float* br0 = (const float*)d_in[8];
    const float* Wc0 = (const float*)d_in[9];
    const float* bc0 = (const float*)d_in[10];
    const float* Wg1 = (const float*)d_in[11];
    const float* bg1 = (const float*)d_in[12];
    const float* Wu1 = (const float*)d_in[13];
    const float* bu1 = (const float*)d_in[14];
    const float* Wr1 = (const float*)d_in[15];
    const float* br1 = (const float*)d_in[16];
    const float* Wc1 = (const float*)d_in[17];
    const float* bc1 = (const float*)d_in[18];
    const float* ipw = (const float*)d_in[19];
    const float* ipb = (const float*)d_in[20];
    const float* opw = (const float*)d_in[21];
    const float* opb = (const float*)d_in[22];
    const float* ow  = (const float*)d_in[23];
    const float* ob  = (const float*)d_in[24];
    float* out = (float*)d_out;

    void *p_deg, *p_cnt, *p_cur, *p_h0, *p_h1, *p_xt, *p_hseq, *p_xw0all, *p_p0all, *p_xw;
    void *p_ipwT, *p_pkWg0, *p_pkpre0, *p_pkurc0, *p_pkWg1, *p_pkurc1, *p_pkqkv;
    cudaGetSymbolAddress(&p_deg, g_deg);
    cudaGetSymbolAddress(&p_cnt, g_cnt);
    cudaGetSymbolAddress(&p_cur, g_cur);
    cudaGetSymbolAddress(&p_h0, g_h0);
    cudaGetSymbolAddress(&p_h1, g_h1);
    cudaGetSymbolAddress(&p_xt, g_xt);
    cudaGetSymbolAddress(&p_hseq, g_hseq);
    cudaGetSymbolAddress(&p_xw0all, g_xw0all);
    cudaGetSymbolAddress(&p_p0all, g_p0all);
    cudaGetSymbolAddress(&p_xw, g_xw);
    cudaGetSymbolAddress(&p_ipwT, g_ipwT);
    cudaGetSymbolAddress(&p_pkWg0, g_pk_Wg0);
    cudaGetSymbolAddress(&p_pkpre0, g_pk_pre0);
    cudaGetSymbolAddress(&p_pkurc0, g_pk_urc0);
    cudaGetSymbolAddress(&p_pkWg1, g_pk_Wg1);
    cudaGetSymbolAddress(&p_pkurc1, g_pk_urc1);
    cudaGetSymbolAddress(&p_pkqkv, g_pk_qkv);

    cudaMemsetAsync(p_deg, 0, Nn * sizeof(float), 0);
    cudaMemsetAsync(p_cnt, 0, Nn * sizeof(int), 0);
    cudaMemsetAsync(p_cur, 0, Nn * sizeof(int), 0);
    cudaMemsetAsync(p_h0, 0, (size_t)Nn * Hh * sizeof(float), 0);
    cudaMemsetAsync(p_h1, 0, (size_t)Nn * Hh * sizeof(float), 0);

    k_transpose<<<(Nn * Ff * Tt + 255) / 256, 256>>>(x);
    k_trW<<<(192 * Hh + 255) / 256, 256>>>(ipw, opw);
    k_deg_hist<<<(Ee + 255) / 256, 256>>>(ei, ea);
    k_dinv<<<(Nn + 255) / 256, 256>>>();
    k_norm<<<(Ee + 255) / 256, 256>>>(ei, ea);
    k_scan<<<1, 1024>>>();
    k_fill<<<(Ee + 255) / 256, 256>>>(ei);

    unsigned* pkWg0  = (unsigned*)p_pkWg0;
    unsigned* pkpre0 = (unsigned*)p_pkpre0;
    unsigned* pkurc0 = (unsigned*)p_pkurc0;
    unsigned* pkWg1  = (unsigned*)p_pkWg1;
    unsigned* pkurc1 = (unsigned*)p_pkurc1;
    unsigned* pkqkv  = (unsigned*)p_pkqkv;
    float* ipwT = (float*)p_ipwT;
    k_pack<<<4, 128>>>(Wg0, 64, 1, pkWg0);
    k_pack<<<12, 128>>>(Wu0, 64, 3, pkpre0 + 0 * 2048);
    k_pack<<<12, 128>>>(Wr0, 64, 3, pkpre0 + 3 * 2048);
    k_pack<<<12, 128>>>(Wc0, 64, 3, pkpre0 + 6 * 2048);
    k_pack<<<8, 128>>>(Wu0 + 96 * Hh, 64, 2, pkurc0 + 0 * 2048);
    k_pack<<<8, 128>>>(Wr0 + 96 * Hh, 64, 2, pkurc0 + 2 * 2048);
    k_pack<<<8, 128>>>(Wc0 + 96 * Hh, 64, 2, pkurc0 + 4 * 2048);
    k_pack<<<8, 128>>>(Wg1, 64, 2, pkWg1);
    k_pack<<<24, 128>>>(Wu1, 64, 6, pkurc1 + 0 * 2048);
    k_pack<<<24, 128>>>(Wr1, 64, 6, pkurc1 + 6 * 2048);
    k_pack<<<24, 128>>>(Wc1, 64, 6, pkurc1 + 12 * 2048);
    k_pack<<<8, 128>>>(ipwT + 0,   192, 2, pkqkv + 0 * 2048);
    k_pack<<<8, 128>>>(ipwT + 64,  192, 2, pkqkv + 2 * 2048);
    k_pack<<<8, 128>>>(ipwT + 128, 192, 2, pkqkv + 4 * 2048);

    // ---- hoisted precomputes ----
    k_mma_g<<<TN / 128, 256>>>((const float*)p_xt, Ff, 1, TN, pkWg0, (float*)p_xw0all);
    k_agg_all<<<(TN + 7) / 8, 256>>>(bg0);
    k_pre0m<<<TN / 128, 256>>>(bu0, br0, bc0);

    const int GB = (Nn + 127) / 128;          // 157
    const int AGG_GRID = (Nn + 7) / 8;        // 2500
    float* h0 = (float*)p_h0;
    float* h1 = (float*)p_h1;

    for (int t = 0; t < Tt; t++) {
        k_urc0x<<<GB, 256>>>((const float*)p_p0all + (size_t)t * Nn * 192, h0, (float*)p_xw);
        k_gcn_agg<<<AGG_GRID, 256>>>(bg1);
        k_urc1m<<<GB, 256>>>(h0, bu1, br1, bc1, h1,
                             (float*)p_hseq + (size_t)t * Nn * Hh);
    }

    k_qkvm<<<TN / 128, 256>>>(ipb);
    k_attn2<<<(Nn + 3) / 4, 128>>>(opb, ow, ob, out);
}

// round 9
// speedup vs baseline: 2.2990x; 1.8963x over previous
#include <cuda_runtime.h>
#include <math.h>
#include <stdint.h>

#define Nn 20000
#define Ff 32
#define Tt 12
#define Hh 64
#define Ee 320000
#define OUTD 12
#define TN (Tt * Nn)

// ---------------- scratch ----------------
static __device__ float g_xt[(size_t)TN * Ff];
static __device__ float g_deg[Nn];
static __device__ float g_dinv[Nn];
static __device__ float g_norm[Ee];
static __device__ int   g_cnt[Nn];
static __device__ int   g_cur[Nn];
static __device__ int   g_rowptr[Nn + 1];
static __device__ int   g_csrsrc[Ee];
static __device__ float g_csrnorm[Ee];
static __device__ float g_xw0all[(size_t)TN * Hh];
static __device__ float g_g0all[(size_t)TN * Hh];
static __device__ float g_p0all[(size_t)TN * 192];
static __device__ float g_xw[(size_t)Nn * Hh];
static __device__ float g_gg[(size_t)Nn * Hh];
static __device__ float g_h0[(size_t)Nn * Hh];
static __device__ float g_h1[(size_t)Nn * Hh];
static __device__ float g_hseq[(size_t)TN * Hh];
static __device__ float g_qkv[(size_t)TN * 192];
static __device__ float g_ipwT[Hh * 192];
static __device__ float g_opwT[Hh * Hh];

// pre-packed tf32 b-fragments
static __device__ unsigned g_pk_Wg0[1 * 2048];
static __device__ unsigned g_pk_pre0[9 * 2048];
static __device__ unsigned g_pk_urc0[6 * 2048];
static __device__ unsigned g_pk_Wg1[2 * 2048];
static __device__ unsigned g_pk_urc1[18 * 2048];
static __device__ unsigned g_pk_qkv[6 * 2048];

__device__ __forceinline__ float sigmoidf_(float x) { return 1.0f / (1.0f + __expf(-x)); }

__device__ __forceinline__ unsigned f2tf32(float f) {
    unsigned r;
    asm("cvt.rna.tf32.f32 %0, %1;" : "=r"(r) : "f"(f));
    return r;
}

__device__ __forceinline__ void mma_tf32(float c[4], const unsigned a[4], unsigned b0, unsigned b1) {
    asm volatile(
        "mma.sync.aligned.m16n8k8.row.col.f32.tf32.tf32.f32 "
        "{%0,%1,%2,%3}, {%4,%5,%6,%7}, {%8,%9}, {%0,%1,%2,%3};"
        : "+f"(c[0]), "+f"(c[1]), "+f"(c[2]), "+f"(c[3])
        : "r"(a[0]), "r"(a[1]), "r"(a[2]), "r"(a[3]), "r"(b0), "r"(b1));
}

__device__ __forceinline__ void load_A_chunk(unsigned a[4][4], const float* __restrict__ A,
                                             int lda, int r0, int r1, bool v0, bool v1,
                                             int k0, int qc) {
#pragma unroll
    for (int s = 0; s < 4; s++) {
        int k = k0 + 8 * s + qc;
        float x0 = v0 ? A[(size_t)r0 * lda + k] : 0.f;
        float x1 = v1 ? A[(size_t)r1 * lda + k] : 0.f;
        float x2 = v0 ? A[(size_t)r0 * lda + k + 4] : 0.f;
        float x3 = v1 ? A[(size_t)r1 * lda + k + 4] : 0.f;
        a[s][0] = f2tf32(x0); a[s][1] = f2tf32(x1);
        a[s][2] = f2tf32(x2); a[s][3] = f2tf32(x3);
    }
}

// A chunk from smem tf32 buffer U[k][72] (64-row tile)
__device__ __forceinline__ void load_A_smemU(unsigned a[4][4], const unsigned* U,
                                             int rl0, int k0, int qc) {
#pragma unroll
    for (int s = 0; s < 4; s++) {
        int k = k0 + 8 * s + qc;
        a[s][0] = U[k * 72 + rl0];
        a[s][1] = U[k * 72 + rl0 + 8];
        a[s][2] = U[(k + 4) * 72 + rl0];
        a[s][3] = U[(k + 4) * 72 + rl0 + 8];
    }
}

__device__ __forceinline__ void mma_gate(float C[8][4], const unsigned a[4][4],
                                         const unsigned* __restrict__ Bpk, int lane) {
    const uint4* B4 = (const uint4*)Bpk;
#pragma unroll
    for (int s = 0; s < 4; s++)
#pragma unroll
        for (int f2 = 0; f2 < 4; f2++) {
            uint4 b = B4[(s * 4 + f2) * 32 + lane];
            mma_tf32(C[2 * f2], a[s], b.x, b.y);
            mma_tf32(C[2 * f2 + 1], a[s], b.z, b.w);
        }
}

// ---------------- weight pack ----------------
__global__ void k_pack(const float* __restrict__ W, int ldw, int nch,
                       unsigned* __restrict__ dst) {
    int tid = blockIdx.x * blockDim.x + threadIdx.x;
    if (tid >= nch * 512) return;
    int c = tid >> 9, r = tid & 511;
    int s = r >> 7, f2 = (r >> 5) & 3, lane = r & 31;
    int qr = lane >> 2, qc = lane & 3;
    int k1 = c * 32 + 8 * s + qc, k2 = k1 + 4;
    int n1 = 16 * f2 + qr, n2 = n1 + 8;
    uint4 o;
    o.x = f2tf32(W[(size_t)k1 * ldw + n1]);
    o.y = f2tf32(W[(size_t)k2 * ldw + n1]);
    o.z = f2tf32(W[(size_t)k1 * ldw + n2]);
    o.w = f2tf32(W[(size_t)k2 * ldw + n2]);
    ((uint4*)dst)[tid] = o;
}

// ---------------- preprocessing ----------------
__global__ void k_transpose(const float* __restrict__ x) {
    int idx = blockIdx.x * blockDim.x + threadIdx.x;
    if (idx >= Nn * Ff * Tt) return;
    int f = idx & (Ff - 1);
    int t = (idx / Ff) % Tt;
    int n = idx / (Ff * Tt);
    g_xt[(size_t)t * Nn * Ff + (size_t)n * Ff + f] = x[(size_t)n * Ff * Tt + (size_t)f * Tt + t];
}

__global__ void k_trW(const float* __restrict__ ipw, const float* __restrict__ opw) {
    int i = blockIdx.x * blockDim.x + threadIdx.x;
    if (i < 192 * Hh) { int r = i / Hh, c = i % Hh; g_ipwT[c * 192 + r] = ipw[i]; }
    if (i < Hh * Hh)  { int r = i / Hh, c = i % Hh; g_opwT[c * Hh + r] = opw[i]; }
}

__global__ void k_deg_hist(const int* __restrict__ ei, const float* __restrict__ ea) {
    int e = blockIdx.x * blockDim.x + threadIdx.x;
    if (e >= Ee) return;
    int d = ei[Ee + e];
    atomicAdd(&g_deg[d], ea[2 * e + 1]);
    atomicAdd(&g_cnt[d], 1);
}

__global__ void k_dinv() {
    int n = blockIdx.x * blockDim.x + threadIdx.x;
    if (n < Nn) g_dinv[n] = rsqrtf(g_deg[n] + 1.0f);
}

__global__ void k_norm(const int* __restrict__ ei, const float* __restrict__ ea) {
    int e = blockIdx.x * blockDim.x + threadIdx.x;
    if (e >= Ee) return;
    g_norm[e] = g_dinv[ei[e]] * ea[2 * e + 1] * g_dinv[ei[Ee + e]];
}

__global__ void k_scan() {
    __shared__ int sbuf[1024];
    __shared__ int s_carry;
    int tid = threadIdx.x;
    if (tid == 0) { s_carry = 0; g_rowptr[0] = 0; }
    __syncthreads();
    for (int base = 0; base < Nn; base += 1024) {
        int v = (base + tid < Nn) ? g_cnt[base + tid] : 0;
        sbuf[tid] = v;
        __syncthreads();
        for (int off = 1; off < 1024; off <<= 1) {
            int t2 = (tid >= off) ? sbuf[tid - off] : 0;
            __syncthreads();
            sbuf[tid] += t2;
            __syncthreads();
        }
        int incl = sbuf[tid] + s_carry;
        if (base + tid < Nn) g_rowptr[base + tid + 1] = incl;
        int total = sbuf[1023];
        __syncthreads();
        if (tid == 0) s_carry += total;
        __syncthreads();
    }
}

__global__ void k_fill(const int* __restrict__ ei) {
    int e = blockIdx.x * blockDim.x + threadIdx.x;
    if (e >= Ee) return;
    int d = ei[Ee + e];
    int pos = g_rowptr[d] + atomicAdd(&g_cur[d], 1);
    g_csrsrc[pos] = ei[e];
    g_csrnorm[pos] = g_norm[e];
}

// ---------------- generic MMA GEMM (128-row blocks, precompute only) --------
__global__ __launch_bounds__(256) void k_mma_g(const float* __restrict__ A, int lda,
                                               int nch, int M,
                                               const unsigned* __restrict__ Bpk,
                                               float* __restrict__ out) {
    int tid = threadIdx.x, lane = tid & 31, w = tid >> 5;
    int qr = lane >> 2, qc = lane & 3;
    int r0 = blockIdx.x * 128 + w * 16 + qr, r1 = r0 + 8;
    bool v0 = r0 < M, v1 = r1 < M;
    float C[8][4] = {};
    for (int c = 0; c < nch; c++) {
        unsigned a[4][4];
        load_A_chunk(a, A, lda, r0, r1, v0, v1, c * 32, qc);
        mma_gate(C, a, Bpk + (size_t)c * 2048, lane);
    }
#pragma unroll
    for (int f = 0; f < 8; f++) {
        int col = 8 * f + 2 * qc;
        if (v0) *(float2*)(out + (size_t)r0 * 64 + col) = make_float2(C[f][0], C[f][1]);
        if (v1) *(float2*)(out + (size_t)r1 * 64 + col) = make_float2(C[f][2], C[f][3]);
    }
}

// ---------------- pre0 (128-row, 3 gates share A) ---------------------------
__global__ __launch_bounds__(256) void k_pre0m(const float* __restrict__ bu,
                                               const float* __restrict__ br,
                                               const float* __restrict__ bc) {
    int tid = threadIdx.x, lane = tid & 31, w = tid >> 5;
    int qr = lane >> 2, qc = lane & 3;
    int r0 = blockIdx.x * 128 + w * 16 + qr, r1 = r0 + 8;   // TN % 128 == 0
    float C[3][8][4] = {};
    for (int ch = 0; ch < 3; ch++) {
        const float* S = ch ? g_g0all : g_xt;
        int lda = ch ? 64 : 32;
        int k0 = (ch == 2) ? 32 : 0;
        unsigned a[4][4];
        load_A_chunk(a, S, lda, r0, r1, true, true, k0, qc);
#pragma unroll
        for (int g = 0; g < 3; g++)
            mma_gate(C[g], a, g_pk_pre0 + ((size_t)g * 3 + ch) * 2048, lane);
    }
#pragma unroll
    for (int g = 0; g < 3; g++) {
        const float* b = (g == 0) ? bu : (g == 1) ? br : bc;
#pragma unroll
        for (int f = 0; f < 8; f++) {
            int col = 8 * f + 2 * qc;
            float2 b2 = *(const float2*)(b + col);
            *(float2*)(g_p0all + (size_t)r0 * 192 + g * 64 + col) =
                make_float2(C[g][f][0] + b2.x, C[g][f][1] + b2.y);
            *(float2*)(g_p0all + (size_t)r1 * 192 + g * 64 + col) =
                make_float2(C[g][f][2] + b2.x, C[g][f][3] + b2.y);
        }
    }
}

// ---------------- qkv (128-row) ----------------------------------------------
__global__ __launch_bounds__(256) void k_qkvm(const float* __restrict__ ipb) {
    int tid = threadIdx.x, lane = tid & 31, w = tid >> 5;
    int qr = lane >> 2, qc = lane & 3;
    int r0 = blockIdx.x * 128 + w * 16 + qr, r1 = r0 + 8;
    float C[3][8][4] = {};
    for (int ch = 0; ch < 2; ch++) {
        unsigned a[4][4];
        load_A_chunk(a, g_hseq, 64, r0, r1, true, true, ch * 32, qc);
#pragma unroll
        for (int g = 0; g < 3; g++)
            mma_gate(C[g], a, g_pk_qkv + ((size_t)g * 2 + ch) * 2048, lane);
    }
#pragma unroll
    for (int g = 0; g < 3; g++) {
#pragma unroll
        for (int f = 0; f < 8; f++) {
            int col = 8 * f + 2 * qc;
            float2 b2 = *(const float2*)(ipb + g * 64 + col);
            *(float2*)(g_qkv + (size_t)r0 * 192 + g * 64 + col) =
                make_float2(C[g][f][0] + b2.x, C[g][f][1] + b2.y);
            *(float2*)(g_qkv + (size_t)r1 * 192 + g * 64 + col) =
                make_float2(C[g][f][2] + b2.x, C[g][f][3] + b2.y);
        }
    }
}

// ---------------- layer0 GCN agg over all t (fp32) ---------------------------
__global__ void k_agg_all(const float* __restrict__ bg) {
    int gw = blockIdx.x * (blockDim.x >> 5) + (threadIdx.x >> 5);
    if (gw >= TN) return;
    int t = gw / Nn, n = gw - t * Nn;
    int lane = threadIdx.x & 31;
    const float* xw = g_xw0all + (size_t)t * Nn * Hh;
    int beg = g_rowptr[n], end = g_rowptr[n + 1];
    float a0 = 0.f, a1 = 0.f;
#pragma unroll 4
    for (int p = beg; p < end; p++) {
        int s = g_csrsrc[p];
        float nm = g_csrnorm[p];
        a0 += nm * xw[(size_t)s * Hh + lane];
        a1 += nm * xw[(size_t)s * Hh + lane + 32];
    }
    float dv = g_dinv[n];
    float dd = dv * dv;
    a0 += dd * xw[(size_t)n * Hh + lane] + bg[lane];
    a1 += dd * xw[(size_t)n * Hh + lane + 32] + bg[lane + 32];
    g_g0all[(size_t)gw * Hh + lane] = sigmoidf_(a0);
    g_g0all[(size_t)gw * Hh + lane + 32] = sigmoidf_(a1);
}

// ---------------- per-step GCN agg (layer1, 1 warp/node) ---------------------
__global__ void k_gcn_agg(const float* __restrict__ bg) {
    int n = blockIdx.x * (blockDim.x >> 5) + (threadIdx.x >> 5);
    if (n >= Nn) return;
    int lane = threadIdx.x & 31;
    int beg = g_rowptr[n], end = g_rowptr[n + 1];
    float a0 = 0.f, a1 = 0.f;
#pragma unroll 4
    for (int p = beg; p < end; p++) {
        int s = g_csrsrc[p];
        float nm = g_csrnorm[p];
        a0 += nm * g_xw[(size_t)s * Hh + lane];
        a1 += nm * g_xw[(size_t)s * Hh + lane + 32];
    }
    float dv = g_dinv[n];
    float dd = dv * dv;
    a0 += dd * g_xw[(size_t)n * Hh + lane] + bg[lane];
    a1 += dd * g_xw[(size_t)n * Hh + lane + 32] + bg[lane + 32];
    g_gg[(size_t)n * Hh + lane] = sigmoidf_(a0);
    g_gg[(size_t)n * Hh + lane + 32] = sigmoidf_(a1);
}

// ---------------- layer0 urc + GRU update + xw=h@Wg1 (64-row, 128 thr) -------
__global__ __launch_bounds__(128, 3) void k_urc0x(const float* __restrict__ p0,
                                                  float* __restrict__ h,
                                                  float* __restrict__ xw) {
    __shared__ unsigned U[64 * 72];      // 18.4KB; warp-disjoint rows
    int tid = threadIdx.x, lane = tid & 31, w = tid >> 5;
    int qr = lane >> 2, qc = lane & 3;
    int rl0 = w * 16 + qr;
    int r0 = blockIdx.x * 64 + rl0, r1 = r0 + 8;
    bool v0 = r0 < Nn, v1 = r1 < Nn;
    float Cu[8][4], Cr[8][4], Cc[8][4];
#pragma unroll
    for (int f = 0; f < 8; f++) {
        int col = 8 * f + 2 * qc;
        float2 z = make_float2(0.f, 0.f);
        float2 u0 = z, u1 = z, rr0 = z, rr1 = z, c0 = z, c1 = z;
        if (v0) {
            u0  = *(const float2*)(p0 + (size_t)r0 * 192 + col);
            rr0 = *(const float2*)(p0 + (size_t)r0 * 192 + 64 + col);
            c0  = *(const float2*)(p0 + (size_t)r0 * 192 + 128 + col);
        }
        if (v1) {
            u1  = *(const float2*)(p0 + (size_t)r1 * 192 + col);
            rr1 = *(const float2*)(p0 + (size_t)r1 * 192 + 64 + col);
            c1  = *(const float2*)(p0 + (size_t)r1 * 192 + 128 + col);
        }
        Cu[f][0] = u0.x;  Cu[f][1] = u0.y;  Cu[f][2] = u1.x;  Cu[f][3] = u1.y;
        Cr[f][0] = rr0.x; Cr[f][1] = rr0.y; Cr[f][2] = rr1.x; Cr[f][3] = rr1.y;
        Cc[f][0] = c0.x;  Cc[f][1] = c0.y;  Cc[f][2] = c1.x;  Cc[f][3] = c1.y;
    }
    for (int ch = 0; ch < 2; ch++) {
        unsigned a[4][4];
        load_A_chunk(a, h, 64, r0, r1, v0, v1, ch * 32, qc);
        mma_gate(Cu, a, g_pk_urc0 + (size_t)(0 + ch) * 2048, lane);
        mma_gate(Cr, a, g_pk_urc0 + (size_t)(2 + ch) * 2048, lane);
    }
    // epilogue1: u=sig, U=tf32(sig(r)*h), stash h in Cr
#pragma unroll
    for (int f = 0; f < 8; f++) {
        int col = 8 * f + 2 * qc;
#pragma unroll
        for (int half = 0; half < 2; half++) {
            int rl = rl0 + 8 * half;
            int row = blockIdx.x * 64 + rl;
            float u0 = sigmoidf_(Cu[f][2 * half + 0]);
            float u1 = sigmoidf_(Cu[f][2 * half + 1]);
            float rg0 = sigmoidf_(Cr[f][2 * half + 0]);
            float rg1 = sigmoidf_(Cr[f][2 * half + 1]);
            Cu[f][2 * half + 0] = u0;
            Cu[f][2 * half + 1] = u1;
            float2 hv = make_float2(0.f, 0.f);
            if (row < Nn) hv = *(const float2*)(h + (size_t)row * 64 + col);
            Cr[f][2 * half + 0] = hv.x;
            Cr[f][2 * half + 1] = hv.y;
            U[col * 72 + rl] = f2tf32(rg0 * hv.x);
            U[(col + 1) * 72 + rl] = f2tf32(rg1 * hv.y);
        }
    }
    __syncwarp();
    for (int ch = 0; ch < 2; ch++) {
        unsigned a[4][4];
        load_A_smemU(a, U, rl0, ch * 32, qc);
        mma_gate(Cc, a, g_pk_urc0 + (size_t)(4 + ch) * 2048, lane);
    }
    // epilogue2: h_new; store h; stage h_new into U for xw pass
#pragma unroll
    for (int f = 0; f < 8; f++) {
        int col = 8 * f + 2 * qc;
#pragma unroll
        for (int half = 0; half < 2; half++) {
            int rl = rl0 + 8 * half;
            int row = blockIdx.x * 64 + rl;
            float hv0 = Cr[f][2 * half + 0], hv1 = Cr[f][2 * half + 1];
            float c0 = tanhf(Cc[f][2 * half + 0]);
            float c1 = tanhf(Cc[f][2 * half + 1]);
            float u0 = Cu[f][2 * half + 0], u1 = Cu[f][2 * half + 1];
            float o0 = u0 * hv0 + (1.f - u0) * c0;
            float o1 = u1 * hv1 + (1.f - u1) * c1;
            if (row < Nn) *(float2*)(h + (size_t)row * 64 + col) = make_float2(o0, o1);
            U[col * 72 + rl] = f2tf32(o0);
            U[(col + 1) * 72 + rl] = f2tf32(o1);
        }
    }
    __syncwarp();
    // xw = h_new @ Wg1
    float Cx[8][4] = {};
    for (int ch = 0; ch < 2; ch++) {
        unsigned a[4][4];
        load_A_smemU(a, U, rl0, ch * 32, qc);
        mma_gate(Cx, a, g_pk_Wg1 + (size_t)ch * 2048, lane);
    }
#pragma unroll
    for (int f = 0; f < 8; f++) {
        int col = 8 * f + 2 * qc;
        if (v0) *(float2*)(xw + (size_t)r0 * 64 + col) = make_float2(Cx[f][0], Cx[f][1]);
        if (v1) *(float2*)(xw + (size_t)r1 * 64 + col) = make_float2(Cx[f][2], Cx[f][3]);
    }
}

// ---------------- layer1 urc + GRU update (64-row, 128 thr) ------------------
__global__ __launch_bounds__(128, 3) void k_urc1m(
    const float* __restrict__ h0,
    const float* __restrict__ bu, const float* __restrict__ br,
    const float* __restrict__ bc,
    float* __restrict__ h, float* __restrict__ hseq) {
    __shared__ unsigned U[64 * 72];
    int tid = threadIdx.x, lane = tid & 31, w = tid >> 5;
    int qr = lane >> 2, qc = lane & 3;
    int rl0 = w * 16 + qr;
    int r0 = blockIdx.x * 64 + rl0, r1 = r0 + 8;
    bool v0 = r0 < Nn, v1 = r1 < Nn;
    float Cu[8][4] = {}, Cr[8][4] = {}, Cc[8][4] = {};
    for (int ch = 0; ch < 6; ch++) {
        const float* S = (ch < 2) ? h0 : (ch < 4) ? g_gg : h;
        unsigned a[4][4];
        load_A_chunk(a, S, 64, r0, r1, v0, v1, (ch & 1) * 32, qc);
        mma_gate(Cu, a, g_pk_urc1 + (size_t)ch * 2048, lane);
        mma_gate(Cr, a, g_pk_urc1 + (size_t)(6 + ch) * 2048, lane);
        if (ch < 4) mma_gate(Cc, a, g_pk_urc1 + (size_t)(12 + ch) * 2048, lane);
    }
    // epilogue1
#pragma unroll
    for (int f = 0; f < 8; f++) {
        int col = 8 * f + 2 * qc;
        float2 bu2 = *(const float2*)(bu + col);
        float2 br2 = *(const float2*)(br + col);
#pragma unroll
        for (int half = 0; half < 2; half++) {
            int rl = rl0 + 8 * half;
            int row = blockIdx.x * 64 + rl;
            float u0 = sigmoidf_(Cu[f][2 * half + 0] + bu2.x);
            float u1 = sigmoidf_(Cu[f][2 * half + 1] + bu2.y);
            float rg0 = sigmoidf_(Cr[f][2 * half + 0] + br2.x);
            float rg1 = sigmoidf_(Cr[f][2 * half + 1] + br2.y);
            Cu[f][2 * half + 0] = u0;
            Cu[f][2 * half + 1] = u1;
            float2 hv = make_float2(0.f, 0.f);
            if (row < Nn) hv = *(const float2*)(h + (size_t)row * 64 + col);
            Cr[f][2 * half + 0] = hv.x;
            Cr[f][2 * half + 1] = hv.y;
            U[col * 72 + rl] = f2tf32(rg0 * hv.x);
            U[(col + 1) * 72 + rl] = f2tf32(rg1 * hv.y);
        }
    }
    __syncwarp();
    for (int ch = 0; ch < 2; ch++) {
        unsigned a[4][4];
        load_A_smemU(a, U, rl0, ch * 32, qc);
        mma_gate(Cc, a, g_pk_urc1 + (size_t)(16 + ch) * 2048, lane);
    }
#pragma unroll
    for (int f = 0; f < 8; f++) {
        int col = 8 * f + 2 * qc;
        float2 bc2 = *(const float2*)(bc + col);
#pragma unroll
        for (int half = 0; half < 2; half++) {
            int row = blockIdx.x * 64 + rl0 + 8 * half;
            if (row >= Nn) continue;
            float hv0 = Cr[f][2 * half + 0], hv1 = Cr[f][2 * half + 1];
            float c0 = tanhf(Cc[f][2 * half + 0] + bc2.x);
            float c1 = tanhf(Cc[f][2 * half + 1] + bc2.y);
            float u0 = Cu[f][2 * half + 0], u1 = Cu[f][2 * half + 1];
            float2 o = make_float2(u0 * hv0 + (1.f - u0) * c0,
                                   u1 * hv1 + (1.f - u1) * c1);
            *(float2*)(h + (size_t)row * 64 + col) = o;
            *(float2*)(hseq + (size_t)row * 64 + col) = o;
        }
    }
}

// ---------------- attention tail -------------------------------------------
__global__ __launch_bounds__(128) void k_attn2(
    const float* __restrict__ opb,
    const float* __restrict__ ow, const float* __restrict__ ob,
    float* __restrict__ out) {
    __shared__ float s_qkv[4][Tt * 192];
    __shared__ float s_sc[4][2 * Tt * Tt];
    __shared__ float s_cs[4][2 * Tt];
    __shared__ float s_ob[4][Hh];
    __shared__ float s_ha[4][Hh];
    int w = threadIdx.x >> 5, lane = threadIdx.x & 31;
    int n = blockIdx.x * 4 + w;
    if (n >= Nn) return;
    float* qkv = s_qkv[w];
    float* sc = s_sc[w];
    float* cs = s_cs[w];
    float* obw = s_ob[w];
    float* haw = s_ha[w];

    for (int i = lane; i < Tt * 48; i += 32) {
        int t = i / 48, r = i % 48;
        *(float4*)&qkv[t * 192 + r * 4] =
            *(const float4*)&g_qkv[((size_t)t * Nn + n) * 192 + r * 4];
    }
    __syncwarp();
    for (int idx = lane; idx < 2 * Tt * Tt; idx += 32) {
        int hd = idx / (Tt * Tt);
        int r = idx % (Tt * Tt);
        int t = r / Tt, s = r % Tt;
        const float* qp = &qkv[t * 192 + hd * 32];
        const float* kp = &qkv[s * 192 + 64 + hd * 32];
        float a = 0.f;
#pragma unroll
        for (int d = 0; d < 32; d++) a += qp[d] * kp[d];
        sc[idx] = a * 0.17677669529663687f;
    }
    __syncwarp();
    if (lane < 2 * Tt) {
        float* row = &sc[lane * Tt];
        float mx = row[0];
#pragma unroll
        for (int s = 1; s < Tt; s++) mx = fmaxf(mx, row[s]);
        float sum = 0.f;
#pragma unroll
        for (int s = 0; s < Tt; s++) { float e = __expf(row[s] - mx); row[s] = e; sum += e; }
        float inv = 1.0f / sum;
#pragma unroll
        for (int s = 0; s < Tt; s++) row[s] *= inv;
    }
    __syncwarp();
    if (lane < 2 * Tt) {
        int hd = lane / Tt, s = lane % Tt;
        float a = 0.f;
#pragma unroll
        for (int t = 0; t < Tt; t++) a += sc[hd * Tt * Tt + t * Tt + s];
        cs[lane] = a * (1.0f / 12.0f);
    }
    __syncwarp();
    for (int m = 0; m < 2; m++) {
        int j = lane + 32 * m;
        int hd = j >> 5;
        float a = 0.f;
#pragma unroll
        for (int s = 0; s < Tt; s++) a += cs[hd * Tt + s] * qkv[s * 192 + 128 + j];
        obw[j] = a;
    }
    __syncwarp();
    for (int m = 0; m < 2; m++) {
        int i = lane + 32 * m;
        float a = opb[i];
#pragma unroll
        for (int j = 0; j < Hh; j++) a += g_opwT[j * Hh + i] * obw[j];
        haw[i] = a;
    }
    __syncwarp();
    if (lane < OUTD) {
        float a = ob[lane];
#pragma unroll
        for (int i = 0; i < Hh; i++) a += haw[i] * ow[(size_t)i * OUTD + lane];
        out[(size_t)n * OUTD + lane] = a;
    }
}

// ---------------- host ----------------
extern "C" void kernel_launch(void* const* d_in, const int* in_sizes, int n_in,
                              void* d_out, int out_size) {
    (void)in_sizes; (void)n_in; (void)out_size;
    const float* x   = (const float*)d_in[0];
    const int*   ei  = (const int*)d_in[1];
    const float* ea  = (const float*)d_in[2];
    const float* Wg0 = (const float*)d_in[3];
    const float* bg0 = (const float*)d_in[4];
    const float* Wu0 = (const float*)d_in[5];
    const float* bu0 = (const float*)d_in[6];
    const float* Wr0 = (const float*)d_in[7];
    const float* br0 = (const float*)d_in[8];
    const float* Wc0 = (const float*)d_in[9];
    const float* bc0 = (const float*)d_in[10];
    const float* Wg1 = (const float*)d_in[11];
    const float* bg1 = (const float*)d_in[12];
    const float* Wu1 = (const float*)d_in[13];
    const float* bu1 = (const float*)d_in[14];
    const float* Wr1 = (const float*)d_in[15];
    const float* br1 = (const float*)d_in[16];
    const float* Wc1 = (const float*)d_in[17];
    const float* bc1 = (const float*)d_in[18];
    const float* ipw = (const float*)d_in[19];
    const float* ipb = (const float*)d_in[20];
    const float* opw = (const float*)d_in[21];
    const float* opb = (const float*)d_in[22];
    const float* ow  = (const float*)d_in[23];
    const float* ob  = (const float*)d_in[24];
    float* out = (float*)d_out;

    void *p_deg, *p_cnt, *p_cur, *p_h0, *p_h1, *p_xt, *p_hseq, *p_xw0all, *p_p0all, *p_xw;
    void *p_ipwT, *p_pkWg0, *p_pkpre0, *p_pkurc0, *p_pkWg1, *p_pkurc1, *p_pkqkv;
    cudaGetSymbolAddress(&p_deg, g_deg);
    cudaGetSymbolAddress(&p_cnt, g_cnt);
    cudaGetSymbolAddress(&p_cur, g_cur);
    cudaGetSymbolAddress(&p_h0, g_h0);
    cudaGetSymbolAddress(&p_h1, g_h1);
    cudaGetSymbolAddress(&p_xt, g_xt);
    cudaGetSymbolAddress(&p_hseq, g_hseq);
    cudaGetSymbolAddress(&p_xw0all, g_xw0all);
    cudaGetSymbolAddress(&p_p0all, g_p0all);
    cudaGetSymbolAddress(&p_xw, g_xw);
    cudaGetSymbolAddress(&p_ipwT, g_ipwT);
    cudaGetSymbolAddress(&p_pkWg0, g_pk_Wg0);
    cudaGetSymbolAddress(&p_pkpre0, g_pk_pre0);
    cudaGetSymbolAddress(&p_pkurc0, g_pk_urc0);
    cudaGetSymbolAddress(&p_pkWg1, g_pk_Wg1);
    cudaGetSymbolAddress(&p_pkurc1, g_pk_urc1);
    cudaGetSymbolAddress(&p_pkqkv, g_pk_qkv);

    cudaMemsetAsync(p_deg, 0, Nn * sizeof(float), 0);
    cudaMemsetAsync(p_cnt, 0, Nn * sizeof(int), 0);
    cudaMemsetAsync(p_cur, 0, Nn * sizeof(int), 0);
    cudaMemsetAsync(p_h0, 0, (size_t)Nn * Hh * sizeof(float), 0);
    cudaMemsetAsync(p_h1, 0, (size_t)Nn * Hh * sizeof(float), 0);

    k_transpose<<<(Nn * Ff * Tt + 255) / 256, 256>>>(x);
    k_trW<<<(192 * Hh + 255) / 256, 256>>>(ipw, opw);
    k_deg_hist<<<(Ee + 255) / 256, 256>>>(ei, ea);
    k_dinv<<<(Nn + 255) / 256, 256>>>();
    k_norm<<<(Ee + 255) / 256, 256>>>(ei, ea);
    k_scan<<<1, 1024>>>();
    k_fill<<<(Ee + 255) / 256, 256>>>(ei);

    unsigned* pkWg0  = (unsigned*)p_pkWg0;
    unsigned* pkpre0 = (unsigned*)p_pkpre0;
    unsigned* pkurc0 = (unsigned*)p_pkurc0;
    unsigned* pkWg1  = (unsigned*)p_pkWg1;
    unsigned* pkurc1 = (unsigned*)p_pkurc1;
    unsigned* pkqkv  = (unsigned*)p_pkqkv;
    float* ipwT = (float*)p_ipwT;
    k_pack<<<4, 128>>>(Wg0, 64, 1, pkWg0);
    k_pack<<<12, 128>>>(Wu0, 64, 3, pkpre0 + 0 * 2048);
    k_pack<<<12, 128>>>(Wr0, 64, 3, pkpre0 + 3 * 2048);
    k_pack<<<12, 128>>>(Wc0, 64, 3, pkpre0 + 6 * 2048);
    k_pack<<<8, 128>>>(Wu0 + 96 * Hh, 64, 2, pkurc0 + 0 * 2048);
    k_pack<<<8, 128>>>(Wr0 + 96 * Hh, 64, 2, pkurc0 + 2 * 2048);
    k_pack<<<8, 128>>>(Wc0 + 96 * Hh, 64, 2, pkurc0 + 4 * 2048);
    k_pack<<<8, 128>>>(Wg1, 64, 2, pkWg1);
    k_pack<<<24, 128>>>(Wu1, 64, 6, pkurc1 + 0 * 2048);
    k_pack<<<24, 128>>>(Wr1, 64, 6, pkurc1 + 6 * 2048);
    k_pack<<<24, 128>>>(Wc1, 64, 6, pkurc1 + 12 * 2048);
    k_pack<<<8, 128>>>(ipwT + 0,   192, 2, pkqkv + 0 * 2048);
    k_pack<<<8, 128>>>(ipwT + 64,  192, 2, pkqkv + 2 * 2048);
    k_pack<<<8, 128>>>(ipwT + 128, 192, 2, pkqkv + 4 * 2048);

    // ---- hoisted precomputes ----
    k_mma_g<<<TN / 128, 256>>>((const float*)p_xt, Ff, 1, TN, pkWg0, (float*)p_xw0all);
    k_agg_all<<<(TN + 7) / 8, 256>>>(bg0);
    k_pre0m<<<TN / 128, 256>>>(bu0, br0, bc0);

    const int GB = (Nn + 63) / 64;            // 313 (64-row tiles, 3 blocks/SM)
    const int AGG_GRID = (Nn + 7) / 8;        // 2500
    float* h0 = (float*)p_h0;
    float* h1 = (float*)p_h1;

    for (int t = 0; t < Tt; t++) {
        k_urc0x<<<GB, 128>>>((const float*)p_p0all + (size_t)t * Nn * 192, h0, (float*)p_xw);
        k_gcn_agg<<<AGG_GRID, 256>>>(bg1);
        k_urc1m<<<GB, 128>>>(h0, bu1, br1, bc1, h1,
                             (float*)p_hseq + (size_t)t * Nn * Hh);
    }

    k_qkvm<<<TN / 128, 256>>>(ipb);
    k_attn2<<<(Nn + 3) / 4, 128>>>(opb, ow, ob, out);
}